// round 8
// baseline (speedup 1.0000x reference)
#include <cuda_runtime.h>
#include <cstdint>

#define NTH    128
#define MAX_E  800000
#define NCAP   50048

// ---- mlp kernel smem layout (bytes) ----
#define SM_ROWS 0          // int[64]
#define SM_COLS 256        // int[64]
#define SM_EIDX 512        // int[64]
#define SM_B2   768        // float[128]
#define SM_A    1536       // 64 rows x 144 B: 9216
#define SM_W1E  10752      // 128 rows x 144 B: 18432
#define SM_W2   29184      // 128 rows x 272 B: 34816
#define SMEM_MLP 64000

// ---- pcomp kernel smem layout ----
#define PC_B1   0          // float[128]
#define PC_A    1024       // 128 rows x 272 B: 34816
#define PC_W    35840      // 128 rows x 272 B: 34816
#define SMEM_PC 70656

__device__ int g_cnt[2];
__device__ int g_list[2 * MAX_E];
// packed fp16 weight images, hidden-split halves, smem (ldmatrix) layout
__device__ uint32_t gW1eh[4 * 128 * 36];    // [f*2+hh][n<128][kpair<32 +pad]
__device__ uint32_t gW1xh[4 * 128 * 68];    // [f*2+hh][n<128][kpair<64 +pad]
__device__ uint32_t gW2h [4 * 128 * 68];    // [f*2+hh][n<128][kpair<64 +pad]
// P[f][node][q<4][hh<2][j2<8][4] = x[node]@W1x_f + b1_f (fragment-permuted)
__device__ float g_P[2 * (size_t)NCAP * 256];

// ---------------- helpers ----------------
static __device__ __forceinline__ uint32_t smem_u32(const void* p) {
    uint32_t a;
    asm("{ .reg .u64 t; cvta.to.shared.u64 t, %1; cvt.u32.u64 %0, t; }"
        : "=r"(a) : "l"(p));
    return a;
}
static __device__ __forceinline__ uint32_t pack_h2(float lo, float hi) {
    uint32_t r;
    asm("cvt.rn.f16x2.f32 %0, %1, %2;" : "=r"(r) : "f"(hi), "f"(lo));
    return r;
}
static __device__ __forceinline__ void sts128(uint32_t a, uint32_t r0, uint32_t r1,
                                              uint32_t r2, uint32_t r3) {
    asm volatile("st.shared.v4.b32 [%0], {%1,%2,%3,%4};"
                 :: "r"(a), "r"(r0), "r"(r1), "r"(r2), "r"(r3) : "memory");
}
static __device__ __forceinline__ void ldsm_x4(uint32_t r[4], uint32_t addr) {
    asm volatile("ldmatrix.sync.aligned.m8n8.x4.shared.b16 {%0,%1,%2,%3}, [%4];"
                 : "=r"(r[0]), "=r"(r[1]), "=r"(r[2]), "=r"(r[3]) : "r"(addr));
}
static __device__ __forceinline__ void mma_f16(float d[4], const uint32_t a[4],
                                               const uint32_t b[2]) {
    asm("mma.sync.aligned.m16n8k16.row.col.f32.f16.f16.f32 "
        "{%0,%1,%2,%3}, {%4,%5,%6,%7}, {%8,%9}, {%0,%1,%2,%3};"
        : "+f"(d[0]), "+f"(d[1]), "+f"(d[2]), "+f"(d[3])
        : "r"(a[0]), "r"(a[1]), "r"(a[2]), "r"(a[3]), "r"(b[0]), "r"(b[1]));
}
static __device__ __forceinline__ void red_add(float* p, float v) {
    asm volatile("red.global.add.f32 [%0], %1;" :: "l"(p), "f"(v) : "memory");
}
static __device__ __forceinline__ void cpa16(uint32_t d, const uint32_t* s) {
    asm volatile("cp.async.ca.shared.global [%0], [%1], 16;"
                 :: "r"(d), "l"(s) : "memory");
}
#define CP_COMMIT() asm volatile("cp.async.commit_group;" ::: "memory")
#define CP_WAIT(n)  asm volatile("cp.async.wait_group %0;" :: "n"(n) : "memory")

// ---------------- setup kernels ----------------
__global__ void reset_kernel() { g_cnt[0] = 0; g_cnt[1] = 0; }

// fp16 images: W1e 16384, W1x 32768, W2 32768 pack-pairs
__global__ void prep_kernel(const float* __restrict__ W1o, const float* __restrict__ W1i,
                            const float* __restrict__ W2o, const float* __restrict__ W2i) {
    int idx = blockIdx.x * 256 + threadIdx.x;
    if (idx < 16384) {                          // W1e: [fh][nl<128][p<32]
        int p = idx & 31; int t = idx >> 5;
        int nl = t & 127; int fh = t >> 7;
        int f = fh >> 1, hh = fh & 1;
        const float* W = f ? W1i : W1o;
        gW1eh[(fh * 128 + nl) * 36 + p] =
            pack_h2(W[(128 + 2 * p) * 256 + hh * 128 + nl],
                    W[(129 + 2 * p) * 256 + hh * 128 + nl]);
    } else if (idx < 49152) {                   // W1x: [fh][nl<128][p<64]
        int i = idx - 16384;
        int p = i & 63; int t = i >> 6;
        int nl = t & 127; int fh = t >> 7;
        int f = fh >> 1, hh = fh & 1;
        const float* W = f ? W1i : W1o;
        gW1xh[(fh * 128 + nl) * 68 + p] =
            pack_h2(W[(2 * p) * 256 + hh * 128 + nl],
                    W[(2 * p + 1) * 256 + hh * 128 + nl]);
    } else if (idx < 81920) {                   // W2: [fh][nl<128][p<64]
        int i = idx - 49152;
        int p = i & 63; int t = i >> 6;
        int nl = t & 127; int fh = t >> 7;
        int f = fh >> 1, hh = fh & 1;
        const float* W = f ? W2i : W2o;
        gW2h[(fh * 128 + nl) * 68 + p] =
            pack_h2(W[(hh * 128 + 2 * p) * 128 + nl],
                    W[(hh * 128 + 2 * p + 1) * 128 + nl]);
    }
}

__global__ void partition_kernel(const int* __restrict__ ei, int E) {
    __shared__ int s_cnt[2], s_base[2];
    int tid = threadIdx.x;
    if (tid < 2) s_cnt[tid] = 0;
    __syncthreads();
    int e = blockIdx.x * blockDim.x + tid;
    bool valid = e < E;
    int r = 0, c = 0;
    if (valid) { r = ei[e]; c = ei[E + e]; }
    int lane = tid & 31;
    bool po = valid && (r < c);
    bool pi = valid && (r > c);
    unsigned mo = __ballot_sync(0xffffffffu, po);
    unsigned mi = __ballot_sync(0xffffffffu, pi);
    int lo = __ffs(mo) - 1, li = __ffs(mi) - 1;
    int wo = 0, wi = 0;
    if (mo && lane == lo) wo = atomicAdd(&s_cnt[0], __popc(mo));
    if (mi && lane == li) wi = atomicAdd(&s_cnt[1], __popc(mi));
    __syncthreads();
    if (tid == 0) s_base[0] = atomicAdd(&g_cnt[0], s_cnt[0]);
    if (tid == 1) s_base[1] = atomicAdd(&g_cnt[1], s_cnt[1]);
    __syncthreads();
    if (mo) wo = __shfl_sync(0xffffffffu, wo, lo);
    if (mi) wi = __shfl_sync(0xffffffffu, wi, li);
    unsigned lt = (1u << lane) - 1u;
    if (po) g_list[s_base[0] + wo + __popc(mo & lt)] = e;
    if (pi) g_list[MAX_E + s_base[1] + wi + __popc(mi & lt)] = e;
}

// ---------------- P precompute: P = x @ W1x + b1 (per flavor/half) ----------
__global__ __launch_bounds__(256, 2)
void pcomp_kernel(const float* __restrict__ x,
                  const float* __restrict__ b1o, const float* __restrict__ b1i,
                  int N) {
    int f = blockIdx.y;
    int hh = blockIdx.x & 1;
    int base = (blockIdx.x >> 1) * 128;
    if (base >= N) return;
    const float* b1 = f ? b1i : b1o;

    extern __shared__ __align__(16) char smem[];
    uint32_t sb = smem_u32(smem);
    uint32_t sbA = sb + PC_A, sbW = sb + PC_W;
    int tid = threadIdx.x, wid = tid >> 5, lane = tid & 31;

    // stream W1x half image: 2176 x 16B
    {
        const uint32_t* src = gW1xh + (size_t)(f * 2 + hh) * 128 * 68;
        #pragma unroll
        for (int i = 0; i < 9; i++) {
            int s = tid + i * 256;
            if (s < 2176) cpa16(sbW + s * 16, src + s * 4);
        }
        CP_COMMIT();
    }
    if (tid < 128) ((float*)(smem + PC_B1))[tid] = b1[hh * 128 + tid];

    // gather x rows -> f16, stride 272 B
    {
        int r = tid & 127, h = tid >> 7;
        int node = min(base + r, N - 1);
        const float4* xr = (const float4*)(x + (size_t)node * 128);
        #pragma unroll
        for (int q = 0; q < 8; q++) {
            float4 a = xr[h * 16 + 2 * q], b = xr[h * 16 + 2 * q + 1];
            sts128(sbA + r * 272 + h * 128 + q * 16,
                   pack_h2(a.x, a.y), pack_h2(a.z, a.w),
                   pack_h2(b.x, b.y), pack_h2(b.z, b.w));
        }
    }
    CP_WAIT(0);
    __syncthreads();

    uint32_t aB = sbA + (wid * 16 + (lane & 15)) * 272 + (lane >> 4) * 16;
    uint32_t bB = sbW + (uint32_t)((lane & 7) + ((lane >> 4) << 3)) * 272
                + (uint32_t)(((lane >> 3) & 1) << 4);

    float acc[16][4];
    #pragma unroll
    for (int j = 0; j < 16; j++)
        #pragma unroll
        for (int p = 0; p < 4; p++) acc[j][p] = 0.0f;

    for (int s = 0; s < 8; s++) {
        uint32_t af[4]; ldsm_x4(af, aB + s * 32);
        #pragma unroll
        for (int nt2 = 0; nt2 < 8; nt2++) {
            uint32_t bf4[4];
            ldsm_x4(bf4, bB + nt2 * 4352 + s * 32);
            mma_f16(acc[2 * nt2],     af, bf4);
            mma_f16(acc[2 * nt2 + 1], af, bf4 + 2);
        }
    }

    // epilogue: + b1 half, write fragment-permuted P half-rows
    {
        const float* b1s = (const float*)(smem + PC_B1);
        int q = lane & 3, t2 = 2 * q;
        int m1 = wid * 16 + (lane >> 2), m2 = m1 + 8;
        int n1 = base + m1, n2 = base + m2;
        float* p1 = g_P + ((size_t)f * NCAP + n1) * 256 + q * 64 + hh * 32;
        float* p2 = g_P + ((size_t)f * NCAP + n2) * 256 + q * 64 + hh * 32;
        #pragma unroll
        for (int j = 0; j < 16; j += 2) {
            if (n1 < N) {
                float4 v = { acc[j][0]     + b1s[8 * j + t2],
                             acc[j][1]     + b1s[8 * j + t2 + 1],
                             acc[j + 1][0] + b1s[8 * (j + 1) + t2],
                             acc[j + 1][1] + b1s[8 * (j + 1) + t2 + 1] };
                *(float4*)(p1 + j * 2) = v;
            }
            if (n2 < N) {
                float4 v = { acc[j][2]     + b1s[8 * j + t2],
                             acc[j][3]     + b1s[8 * j + t2 + 1],
                             acc[j + 1][2] + b1s[8 * (j + 1) + t2],
                             acc[j + 1][3] + b1s[8 * (j + 1) + t2 + 1] };
                *(float4*)(p2 + j * 2) = v;
            }
        }
    }
}

// ---------------- main edge-MLP kernel (64 edges x half hidden per CTA) ----
__global__ __launch_bounds__(NTH, 3)
void mlp_kernel(const int* __restrict__ ei, const float* __restrict__ ea,
                const float* __restrict__ b2o, const float* __restrict__ b2i,
                int E, float* __restrict__ out) {
    int f = blockIdx.y;
    int hh = blockIdx.x & 1;
    int cnt = g_cnt[f];
    int base = (blockIdx.x >> 1) * 64;
    if (base >= cnt) return;
    int nvalid = min(64, cnt - base);
    const int* list = g_list + f * MAX_E;
    int colOff = f ? 0 : 128;
    const float* b2 = f ? b2i : b2o;
    int fh = f * 2 + hh;

    extern __shared__ __align__(16) char smem[];
    uint32_t sb = smem_u32(smem);
    uint32_t sbA = sb + SM_A;
    int tid = threadIdx.x, wid = tid >> 5, lane = tid & 31;

    // stream W1e half (group 0): 1152 x 16B;  W2 half (group 1): 2176 x 16B
    {
        const uint32_t* src = gW1eh + (size_t)fh * 128 * 36;
        #pragma unroll
        for (int i = 0; i < 9; i++) {
            int s = tid + i * NTH;
            cpa16(sb + SM_W1E + s * 16, src + s * 4);
        }
        CP_COMMIT();
    }
    {
        const uint32_t* src = gW2h + (size_t)fh * 128 * 68;
        #pragma unroll
        for (int i = 0; i < 17; i++) {
            int s = tid + i * NTH;
            cpa16(sb + SM_W2 + s * 16, src + s * 4);
        }
        CP_COMMIT();
    }

    // headers
    if (tid < 64) {
        int e = list[base + min(tid, nvalid - 1)];
        ((int*)(smem + SM_EIDX))[tid] = e;
        ((int*)(smem + SM_ROWS))[tid] = ei[e];
        ((int*)(smem + SM_COLS))[tid] = ei[E + e];
    }
    ((float*)(smem + SM_B2))[tid] = b2[tid];
    __syncthreads();

    // ---- acc1 init from P half-rows (fragment-permuted) ----
    float acc1[16][4];
    int q = lane & 3;
    int m1 = wid * 16 + (lane >> 2), m2 = m1 + 8;
    {
        int node1 = ((const int*)(smem + SM_COLS))[m1];
        int node2 = ((const int*)(smem + SM_COLS))[m2];
        const float4* p1 = (const float4*)(g_P + ((size_t)f * NCAP + node1) * 256
                                           + q * 64 + hh * 32);
        const float4* p2 = (const float4*)(g_P + ((size_t)f * NCAP + node2) * 256
                                           + q * 64 + hh * 32);
        #pragma unroll
        for (int i4 = 0; i4 < 8; i4++) {
            int j = 2 * i4;
            float4 v = p1[i4];
            acc1[j][0] = v.x; acc1[j][1] = v.y;
            acc1[j + 1][0] = v.z; acc1[j + 1][1] = v.w;
            float4 w = p2[i4];
            acc1[j][2] = w.x; acc1[j][3] = w.y;
            acc1[j + 1][2] = w.z; acc1[j + 1][3] = w.w;
        }
    }

    // ---- gather A = edge_attr as f16, stride 144 B (64 rows) ----
    {
        int r = tid >> 1, h = tid & 1;
        int eidx = ((const int*)(smem + SM_EIDX))[r];
        const float4* er = (const float4*)(ea + (size_t)eidx * 64);
        #pragma unroll
        for (int qq = 0; qq < 4; qq++) {
            float4 a = er[h * 8 + 2 * qq], b = er[h * 8 + 2 * qq + 1];
            sts128(sbA + r * 144 + h * 64 + qq * 16,
                   pack_h2(a.x, a.y), pack_h2(a.z, a.w),
                   pack_h2(b.x, b.y), pack_h2(b.z, b.w));
        }
    }
    CP_WAIT(1);          // W1e resident
    __syncthreads();

    uint32_t aB = sbA + (wid * 16 + (lane & 15)) * 144 + (lane >> 4) * 16;
    uint32_t bo144 = (uint32_t)((lane & 7) + ((lane >> 4) << 3)) * 144
                   + (uint32_t)(((lane >> 3) & 1) << 4);
    uint32_t bo272 = (uint32_t)((lane & 7) + ((lane >> 4) << 3)) * 272
                   + (uint32_t)(((lane >> 3) & 1) << 4);

    // ---- GEMM1: acc1 += A_ea[64x64] @ W1e_half (4 k16-steps, n=128) ----
    {
        uint32_t bW = sb + SM_W1E + bo144;
        #pragma unroll
        for (int s = 0; s < 4; s++) {
            uint32_t af[4]; ldsm_x4(af, aB + s * 32);
            #pragma unroll
            for (int nt2 = 0; nt2 < 8; nt2++) {
                uint32_t bf4[4];
                ldsm_x4(bf4, bW + nt2 * 2304 + s * 32);
                mma_f16(acc1[2 * nt2],     af, bf4);
                mma_f16(acc1[2 * nt2 + 1], af, bf4 + 2);
            }
        }
    }
    CP_WAIT(0);          // W2 resident
    __syncthreads();

    // ---- GEMM2: out2[64x128] += relu(h_half) @ W2_half (8 k16-steps) ----
    float acc2[16][4];
    #pragma unroll
    for (int j = 0; j < 16; j++)
        #pragma unroll
        for (int p = 0; p < 4; p++) acc2[j][p] = 0.0f;

    {
        uint32_t bW = sb + SM_W2 + bo272;
        #pragma unroll
        for (int s2 = 0; s2 < 8; s2++) {
            int j = 2 * s2;
            uint32_t af[4];
            af[0] = pack_h2(fmaxf(acc1[j][0], 0.f),     fmaxf(acc1[j][1], 0.f));
            af[1] = pack_h2(fmaxf(acc1[j][2], 0.f),     fmaxf(acc1[j][3], 0.f));
            af[2] = pack_h2(fmaxf(acc1[j + 1][0], 0.f), fmaxf(acc1[j + 1][1], 0.f));
            af[3] = pack_h2(fmaxf(acc1[j + 1][2], 0.f), fmaxf(acc1[j + 1][3], 0.f));
            #pragma unroll
            for (int nt2 = 0; nt2 < 8; nt2++) {
                uint32_t bf4[4];
                ldsm_x4(bf4, bW + nt2 * 4352 + s2 * 32);
                mma_f16(acc2[2 * nt2],     af, bf4);
                mma_f16(acc2[2 * nt2 + 1], af, bf4 + 2);
            }
        }
    }

    // ---- epilogue: (+ b2 only in hh==0 CTA), scatter-add valid rows ----
    {
        const float* b2s = (const float*)(smem + SM_B2);
        const int* rows = (const int*)(smem + SM_ROWS);
        bool ok1 = m1 < nvalid, ok2 = m2 < nvalid;
        float* o1 = ok1 ? (out + (size_t)rows[m1] * 256 + colOff) : out;
        float* o2 = ok2 ? (out + (size_t)rows[m2] * 256 + colOff) : out;
        int t2 = 2 * q;
        float bs = hh ? 0.0f : 1.0f;     // add b2 once per edge (hh==0 half)
        #pragma unroll
        for (int nt = 0; nt < 16; nt++) {
            int n0 = 8 * nt + t2;
            if (ok1) {
                red_add(o1 + n0,     acc2[nt][0] + bs * b2s[n0]);
                red_add(o1 + n0 + 1, acc2[nt][1] + bs * b2s[n0 + 1]);
            }
            if (ok2) {
                red_add(o2 + n0,     acc2[nt][2] + bs * b2s[n0]);
                red_add(o2 + n0 + 1, acc2[nt][3] + bs * b2s[n0 + 1]);
            }
        }
    }
}

// ---------------- host launch ----------------
extern "C" void kernel_launch(void* const* d_in, const int* in_sizes, int n_in,
                              void* d_out, int out_size) {
    const float* x   = (const float*)d_in[0];
    const int*   ei  = (const int*)  d_in[1];
    const float* ea  = (const float*)d_in[2];
    const float* W1o = (const float*)d_in[3];
    const float* b1o = (const float*)d_in[4];
    const float* W2o = (const float*)d_in[5];
    const float* b2o = (const float*)d_in[6];
    const float* W1i = (const float*)d_in[7];
    const float* b1i = (const float*)d_in[8];
    const float* W2i = (const float*)d_in[9];
    const float* b2i = (const float*)d_in[10];
    float* out = (float*)d_out;
    int E = in_sizes[1] / 2;
    int N = in_sizes[0] / 128;
    if (N > NCAP) N = NCAP;

    static bool attr_set = false;
    if (!attr_set) {
        cudaFuncSetAttribute(mlp_kernel, cudaFuncAttributeMaxDynamicSharedMemorySize,
                             SMEM_MLP);
        cudaFuncSetAttribute(pcomp_kernel, cudaFuncAttributeMaxDynamicSharedMemorySize,
                             SMEM_PC);
        attr_set = true;
    }

    cudaMemsetAsync(d_out, 0, (size_t)out_size * sizeof(float));
    reset_kernel<<<1, 1>>>();
    prep_kernel<<<320, 256>>>(W1o, W1i, W2o, W2i);
    partition_kernel<<<(E + 511) / 512, 512>>>(ei, E);
    pcomp_kernel<<<dim3(((N + 127) / 128) * 2, 2), 256, SMEM_PC>>>(x, b1o, b1i, N);

    dim3 grid(((E + 63) / 64) * 2, 2);
    mlp_kernel<<<grid, NTH, SMEM_MLP>>>(ei, ea, b2o, b2i, E, out);
}

// round 9
// speedup vs baseline: 1.0470x; 1.0470x over previous
#include <cuda_runtime.h>
#include <cstdint>

#define TILE   128
#define NTH    256
#define MAX_E  800000
#define NCAP   50048

// ---- mlp kernel smem layout (bytes) ----
#define SM_ROWS 0          // int[128]
#define SM_COLS 512        // int[128]
#define SM_EIDX 1024       // int[128]
#define SM_B2   1536       // float[128]
#define SM_A    2048       // 128 rows x 144 B: 18432
#define SM_W1E  20480      // 256 rows x 144 B: 36864
#define SM_W2   57344      // 128 rows x 528 B: 67584
#define SMEM_MLP 124928
// epilogue staging (after GEMMs, reuses A/W1E/W2 space)
#define SM_STAGE 2048      // 128 rows x 132 floats: 67584 -> ends 69632
#define SM_SEG   69632     // int nseg + int seg_start[128]

// ---- pcomp kernel smem layout ----
#define PC_B1   0          // float[256]
#define PC_A    1024       // 128 rows x 272 B: 34816
#define PC_W    35840      // 256 rows x 272 B: 69632
#define SMEM_PC 105472

__device__ int g_cnt[2];
__device__ int g_list[2 * MAX_E];
__device__ int g_hist[2 * NCAP];
__device__ int g_hoff[2 * NCAP];
// packed fp16 weight images in smem (ldmatrix) layout, incl. row pads
__device__ uint32_t gW1eh[2 * 256 * 36];    // [f][n<256][kpair<32 +pad]
__device__ uint32_t gW1xh[2 * 256 * 68];    // [f][n<256][kpair<64 +pad]
__device__ uint32_t gW2h [2 * 128 * 132];   // [f][n<128][kpair<128 +pad]
// P[f][node][q<4][j2<16][4] = x[node]@W1x_f + b1_f (fragment-permuted rows)
__device__ float g_P[2 * (size_t)NCAP * 256];

// ---------------- helpers ----------------
static __device__ __forceinline__ uint32_t smem_u32(const void* p) {
    uint32_t a;
    asm("{ .reg .u64 t; cvta.to.shared.u64 t, %1; cvt.u32.u64 %0, t; }"
        : "=r"(a) : "l"(p));
    return a;
}
static __device__ __forceinline__ uint32_t pack_h2(float lo, float hi) {
    uint32_t r;
    asm("cvt.rn.f16x2.f32 %0, %1, %2;" : "=r"(r) : "f"(hi), "f"(lo));
    return r;
}
static __device__ __forceinline__ void sts128(uint32_t a, uint32_t r0, uint32_t r1,
                                              uint32_t r2, uint32_t r3) {
    asm volatile("st.shared.v4.b32 [%0], {%1,%2,%3,%4};"
                 :: "r"(a), "r"(r0), "r"(r1), "r"(r2), "r"(r3) : "memory");
}
static __device__ __forceinline__ void ldsm_x4(uint32_t r[4], uint32_t addr) {
    asm volatile("ldmatrix.sync.aligned.m8n8.x4.shared.b16 {%0,%1,%2,%3}, [%4];"
                 : "=r"(r[0]), "=r"(r[1]), "=r"(r[2]), "=r"(r[3]) : "r"(addr));
}
static __device__ __forceinline__ void mma_f16(float d[4], const uint32_t a[4],
                                               const uint32_t b[2]) {
    asm("mma.sync.aligned.m16n8k16.row.col.f32.f16.f16.f32 "
        "{%0,%1,%2,%3}, {%4,%5,%6,%7}, {%8,%9}, {%0,%1,%2,%3};"
        : "+f"(d[0]), "+f"(d[1]), "+f"(d[2]), "+f"(d[3])
        : "r"(a[0]), "r"(a[1]), "r"(a[2]), "r"(a[3]), "r"(b[0]), "r"(b[1]));
}
static __device__ __forceinline__ void red_add(float* p, float v) {
    asm volatile("red.global.add.f32 [%0], %1;" :: "l"(p), "f"(v) : "memory");
}
static __device__ __forceinline__ void cpa16(uint32_t d, const uint32_t* s) {
    asm volatile("cp.async.ca.shared.global [%0], [%1], 16;"
                 :: "r"(d), "l"(s) : "memory");
}
#define CP_COMMIT() asm volatile("cp.async.commit_group;" ::: "memory")
#define CP_WAIT(n)  asm volatile("cp.async.wait_group %0;" :: "n"(n) : "memory")

// ---------------- setup / sort kernels ----------------
__global__ void reset_kernel() {          // zero histograms
    int i = blockIdx.x * 1024 + threadIdx.x;
    if (i < 2 * NCAP) g_hist[i] = 0;
}

__global__ void hist_kernel(const int* __restrict__ ei, int E) {
    int e = blockIdx.x * blockDim.x + threadIdx.x;
    if (e >= E) return;
    int r = ei[e], c = ei[E + e];
    if (r < c) atomicAdd(&g_hist[r], 1);
    else if (r > c) atomicAdd(&g_hist[NCAP + r], 1);
}

__global__ void scan_kernel() {           // one block per flavor, 1024 threads
    __shared__ int s_part[1024];
    int f = blockIdx.x, t = threadIdx.x;
    const int CH = 49;                    // 1024*49 >= NCAP
    int base = t * CH;
    int sum = 0;
    for (int i = 0; i < CH; i++) {
        int idx = base + i;
        if (idx < NCAP) sum += g_hist[f * NCAP + idx];
    }
    s_part[t] = sum;
    __syncthreads();
    for (int d = 1; d < 1024; d <<= 1) {
        int v = (t >= d) ? s_part[t - d] : 0;
        __syncthreads();
        s_part[t] += v;
        __syncthreads();
    }
    int run = s_part[t] - sum;            // exclusive prefix for this chunk
    if (t == 1023) g_cnt[f] = s_part[1023];
    for (int i = 0; i < CH; i++) {
        int idx = base + i;
        if (idx < NCAP) {
            int cval = g_hist[f * NCAP + idx];
            g_hoff[f * NCAP + idx] = run;
            run += cval;
        }
    }
}

__global__ void scatter_kernel(const int* __restrict__ ei, int E) {
    int e = blockIdx.x * blockDim.x + threadIdx.x;
    if (e >= E) return;
    int r = ei[e], c = ei[E + e];
    if (r < c) {
        int pos = atomicAdd(&g_hoff[r], 1);
        g_list[pos] = e;
    } else if (r > c) {
        int pos = atomicAdd(&g_hoff[NCAP + r], 1);
        g_list[MAX_E + pos] = e;
    }
}

// fp16 images: W1e 16384, W1x 32768, W2 32768 pack-pairs
__global__ void prep_kernel(const float* __restrict__ W1o, const float* __restrict__ W1i,
                            const float* __restrict__ W2o, const float* __restrict__ W2i) {
    int idx = blockIdx.x * 256 + threadIdx.x;
    if (idx < 16384) {                          // W1e: [f][nl<256][p<32]
        int p = idx & 31; int t = idx >> 5;
        int nl = t & 255; int f = t >> 8;
        const float* W = f ? W1i : W1o;
        gW1eh[(f * 256 + nl) * 36 + p] =
            pack_h2(W[(128 + 2 * p) * 256 + nl], W[(129 + 2 * p) * 256 + nl]);
    } else if (idx < 49152) {                   // W1x: [f][nl<256][p<64]
        int i = idx - 16384;
        int p = i & 63; int t = i >> 6;
        int nl = t & 255; int f = t >> 8;
        const float* W = f ? W1i : W1o;
        gW1xh[(f * 256 + nl) * 68 + p] =
            pack_h2(W[(2 * p) * 256 + nl], W[(2 * p + 1) * 256 + nl]);
    } else if (idx < 81920) {                   // W2: [f][nl<128][p<128]
        int i = idx - 49152;
        int p = i & 127; int t = i >> 7;
        int nl = t & 127; int f = t >> 7;
        const float* W = f ? W2i : W2o;
        gW2h[(f * 128 + nl) * 132 + p] =
            pack_h2(W[(2 * p) * 128 + nl], W[(2 * p + 1) * 128 + nl]);
    }
}

// ---------------- P precompute: P = x @ W1x + b1 (per flavor) ----------------
__global__ __launch_bounds__(NTH, 1)
void pcomp_kernel(const float* __restrict__ x,
                  const float* __restrict__ b1o, const float* __restrict__ b1i,
                  int N) {
    int f = blockIdx.y;
    int base = blockIdx.x * 128;
    if (base >= N) return;
    const float* b1 = f ? b1i : b1o;

    extern __shared__ __align__(16) char smem[];
    uint32_t sb = smem_u32(smem);
    uint32_t sbA = sb + PC_A, sbW = sb + PC_W;
    int tid = threadIdx.x, wid = tid >> 5, lane = tid & 31;

    {
        const uint32_t* src = gW1xh + (size_t)f * 256 * 68;
        #pragma unroll
        for (int i = 0; i < 17; i++) {
            int s = tid + i * NTH;
            cpa16(sbW + s * 16, src + s * 4);
        }
        CP_COMMIT();
    }
    ((float*)(smem + PC_B1))[tid] = b1[tid];

    {
        int r = tid & 127, h = tid >> 7;
        int node = min(base + r, N - 1);
        const float4* xr = (const float4*)(x + (size_t)node * 128);
        #pragma unroll
        for (int q = 0; q < 8; q++) {
            float4 a = xr[h * 16 + 2 * q], b = xr[h * 16 + 2 * q + 1];
            sts128(sbA + r * 272 + h * 128 + q * 16,
                   pack_h2(a.x, a.y), pack_h2(a.z, a.w),
                   pack_h2(b.x, b.y), pack_h2(b.z, b.w));
        }
    }
    CP_WAIT(0);
    __syncthreads();

    uint32_t aB = sbA + (wid * 16 + (lane & 15)) * 272 + (lane >> 4) * 16;
    uint32_t bB = sbW + (uint32_t)((lane & 7) + ((lane >> 4) << 3)) * 272
                + (uint32_t)(((lane >> 3) & 1) << 4);

    float acc[32][4];
    #pragma unroll
    for (int j = 0; j < 32; j++)
        #pragma unroll
        for (int p = 0; p < 4; p++) acc[j][p] = 0.0f;

    for (int s = 0; s < 8; s++) {
        uint32_t af[4]; ldsm_x4(af, aB + s * 32);
        #pragma unroll
        for (int nt2 = 0; nt2 < 16; nt2++) {
            uint32_t bf4[4];
            ldsm_x4(bf4, bB + nt2 * 4352 + s * 32);
            mma_f16(acc[2 * nt2],     af, bf4);
            mma_f16(acc[2 * nt2 + 1], af, bf4 + 2);
        }
    }

    {
        const float* b1s = (const float*)(smem + PC_B1);
        int q = lane & 3, t2 = 2 * q;
        int m1 = wid * 16 + (lane >> 2), m2 = m1 + 8;
        int n1 = base + m1, n2 = base + m2;
        float* p1 = g_P + ((size_t)f * NCAP + n1) * 256 + q * 64;
        float* p2 = g_P + ((size_t)f * NCAP + n2) * 256 + q * 64;
        #pragma unroll
        for (int j = 0; j < 32; j += 2) {
            if (n1 < N) {
                float4 v = { acc[j][0]     + b1s[8 * j + t2],
                             acc[j][1]     + b1s[8 * j + t2 + 1],
                             acc[j + 1][0] + b1s[8 * (j + 1) + t2],
                             acc[j + 1][1] + b1s[8 * (j + 1) + t2 + 1] };
                *(float4*)(p1 + j * 2) = v;
            }
            if (n2 < N) {
                float4 v = { acc[j][2]     + b1s[8 * j + t2],
                             acc[j][3]     + b1s[8 * j + t2 + 1],
                             acc[j + 1][2] + b1s[8 * (j + 1) + t2],
                             acc[j + 1][3] + b1s[8 * (j + 1) + t2 + 1] };
                *(float4*)(p2 + j * 2) = v;
            }
        }
    }
}

// ---------------- main edge-MLP kernel (sorted edges, staged epilogue) ------
__global__ __launch_bounds__(NTH, 1)
void mlp_kernel(const int* __restrict__ ei, const float* __restrict__ ea,
                const float* __restrict__ b2o, const float* __restrict__ b2i,
                int E, float* __restrict__ out) {
    int f = blockIdx.y;
    int cnt = g_cnt[f];
    int base = blockIdx.x * TILE;
    if (base >= cnt) return;
    int nvalid = min(TILE, cnt - base);
    const int* list = g_list + f * MAX_E;
    int colOff = f ? 0 : 128;
    const float* b2 = f ? b2i : b2o;

    extern __shared__ __align__(16) char smem[];
    uint32_t sb = smem_u32(smem);
    uint32_t sbA = sb + SM_A;
    int tid = threadIdx.x, wid = tid >> 5, lane = tid & 31;

    // stream W1e (group 0): 2304 x 16B;  W2 (group 1): 4224 x 16B
    {
        const uint32_t* src = gW1eh + (size_t)f * 256 * 36;
        #pragma unroll
        for (int i = 0; i < 9; i++) {
            int s = tid + i * NTH;
            cpa16(sb + SM_W1E + s * 16, src + s * 4);
        }
        CP_COMMIT();
    }
    {
        const uint32_t* src = gW2h + (size_t)f * 128 * 132;
        #pragma unroll
        for (int i = 0; i < 17; i++) {
            int s = tid + i * NTH;
            if (s < 4224) cpa16(sb + SM_W2 + s * 16, src + s * 4);
        }
        CP_COMMIT();
    }

    // headers (sorted list -> rows ascending within tile)
    if (tid < TILE) {
        int e = list[base + min(tid, nvalid - 1)];
        ((int*)(smem + SM_EIDX))[tid] = e;
        ((int*)(smem + SM_ROWS))[tid] = ei[e];
        ((int*)(smem + SM_COLS))[tid] = ei[E + e];
    }
    if (tid < 128) ((float*)(smem + SM_B2))[tid] = b2[tid];
    __syncthreads();

    // ---- acc1 init from gathered P rows (fragment-permuted) ----
    float acc1[32][4];
    int q = lane & 3;
    int m1 = wid * 16 + (lane >> 2), m2 = m1 + 8;
    {
        int node1 = ((const int*)(smem + SM_COLS))[m1];
        int node2 = ((const int*)(smem + SM_COLS))[m2];
        const float4* p1 = (const float4*)(g_P + ((size_t)f * NCAP + node1) * 256 + q * 64);
        const float4* p2 = (const float4*)(g_P + ((size_t)f * NCAP + node2) * 256 + q * 64);
        #pragma unroll
        for (int i4 = 0; i4 < 16; i4++) {
            int j = 2 * i4;
            float4 v = p1[i4];
            acc1[j][0] = v.x; acc1[j][1] = v.y;
            acc1[j + 1][0] = v.z; acc1[j + 1][1] = v.w;
            float4 w = p2[i4];
            acc1[j][2] = w.x; acc1[j][3] = w.y;
            acc1[j + 1][2] = w.z; acc1[j + 1][3] = w.w;
        }
    }

    // ---- gather A = edge_attr as f16, stride 144 B ----
    {
        int r = tid & 127, h = tid >> 7;
        int eidx = ((const int*)(smem + SM_EIDX))[r];
        const float4* er = (const float4*)(ea + (size_t)eidx * 64);
        #pragma unroll
        for (int qq = 0; qq < 4; qq++) {
            float4 a = er[h * 8 + 2 * qq], b = er[h * 8 + 2 * qq + 1];
            sts128(sbA + r * 144 + h * 64 + qq * 16,
                   pack_h2(a.x, a.y), pack_h2(a.z, a.w),
                   pack_h2(b.x, b.y), pack_h2(b.z, b.w));
        }
    }
    CP_WAIT(1);
    __syncthreads();

    uint32_t aB = sbA + (wid * 16 + (lane & 15)) * 144 + (lane >> 4) * 16;
    uint32_t bo144 = (uint32_t)((lane & 7) + ((lane >> 4) << 3)) * 144
                   + (uint32_t)(((lane >> 3) & 1) << 4);
    uint32_t bo528 = (uint32_t)((lane & 7) + ((lane >> 4) << 3)) * 528
                   + (uint32_t)(((lane >> 3) & 1) << 4);

    // ---- GEMM1: acc1 += A_ea[128x64] @ W1e ----
    {
        uint32_t bW = sb + SM_W1E + bo144;
        #pragma unroll
        for (int s = 0; s < 4; s++) {
            uint32_t af[4]; ldsm_x4(af, aB + s * 32);
            #pragma unroll
            for (int nt2 = 0; nt2 < 16; nt2++) {
                uint32_t bf4[4];
                ldsm_x4(bf4, bW + nt2 * 2304 + s * 32);
                mma_f16(acc1[2 * nt2],     af, bf4);
                mma_f16(acc1[2 * nt2 + 1], af, bf4 + 2);
            }
        }
    }
    CP_WAIT(0);
    __syncthreads();

    // ---- GEMM2: out2[128x128] = relu(h) @ W2 ----
    float acc2[16][4];
    #pragma unroll
    for (int j = 0; j < 16; j++)
        #pragma unroll
        for (int p = 0; p < 4; p++) acc2[j][p] = 0.0f;

    {
        uint32_t bW = sb + SM_W2 + bo528;
        #pragma unroll
        for (int s2 = 0; s2 < 16; s2++) {
            int j = 2 * s2;
            uint32_t af[4];
            af[0] = pack_h2(fmaxf(acc1[j][0], 0.f),     fmaxf(acc1[j][1], 0.f));
            af[1] = pack_h2(fmaxf(acc1[j][2], 0.f),     fmaxf(acc1[j][3], 0.f));
            af[2] = pack_h2(fmaxf(acc1[j + 1][0], 0.f), fmaxf(acc1[j + 1][1], 0.f));
            af[3] = pack_h2(fmaxf(acc1[j + 1][2], 0.f), fmaxf(acc1[j + 1][3], 0.f));
            #pragma unroll
            for (int nt2 = 0; nt2 < 8; nt2++) {
                uint32_t bf4[4];
                ldsm_x4(bf4, bW + nt2 * 8448 + s2 * 32);
                mma_f16(acc2[2 * nt2],     af, bf4);
                mma_f16(acc2[2 * nt2 + 1], af, bf4 + 2);
            }
        }
    }
    __syncthreads();   // W2/A/W1e smem now dead -> reuse for staging

    // ---- stage acc2 into smem [128 x 132 floats] ----
    {
        float* st = (float*)(smem + SM_STAGE);
        int t2 = 2 * q;
        #pragma unroll
        for (int nt = 0; nt < 16; nt++) {
            int n0 = 8 * nt + t2;
            *(float2*)&st[m1 * 132 + n0] = make_float2(acc2[nt][0], acc2[nt][1]);
            *(float2*)&st[m2 * 132 + n0] = make_float2(acc2[nt][2], acc2[nt][3]);
        }
    }
    // build row segments
    int* nseg = (int*)(smem + SM_SEG);
    int* seg_start = nseg + 1;
    const int* rows_s = (const int*)(smem + SM_ROWS);
    if (tid == 0) *nseg = 0;
    __syncthreads();
    if (tid < nvalid) {
        int r = rows_s[tid];
        bool head = (tid == 0) || (rows_s[tid - 1] != r);
        if (head) {
            int i = atomicAdd(nseg, 1);
            seg_start[i] = tid;
        }
    }
    __syncthreads();

    // ---- segment-reduce + single REDG per (segment, col) ----
    {
        const float* st = (const float*)(smem + SM_STAGE);
        const float* b2s = (const float*)(smem + SM_B2);
        int ns = *nseg;
        int col = tid & 127;
        for (int s = tid >> 7; s < ns; s += 2) {
            int m0 = seg_start[s];
            int r = rows_s[m0];
            float sum = 0.0f;
            int m = m0;
            do { sum += st[m * 132 + col]; m++; }
            while (m < nvalid && rows_s[m] == r);
            sum += (float)(m - m0) * b2s[col];
            red_add(out + (size_t)r * 256 + colOff + col, sum);
        }
    }
}

// ---------------- host launch ----------------
extern "C" void kernel_launch(void* const* d_in, const int* in_sizes, int n_in,
                              void* d_out, int out_size) {
    const float* x   = (const float*)d_in[0];
    const int*   ei  = (const int*)  d_in[1];
    const float* ea  = (const float*)d_in[2];
    const float* W1o = (const float*)d_in[3];
    const float* b1o = (const float*)d_in[4];
    const float* W2o = (const float*)d_in[5];
    const float* b2o = (const float*)d_in[6];
    const float* W1i = (const float*)d_in[7];
    const float* b1i = (const float*)d_in[8];
    const float* W2i = (const float*)d_in[9];
    const float* b2i = (const float*)d_in[10];
    float* out = (float*)d_out;
    int E = in_sizes[1] / 2;
    int N = in_sizes[0] / 128;
    if (N > NCAP) N = NCAP;

    static bool attr_set = false;
    if (!attr_set) {
        cudaFuncSetAttribute(mlp_kernel, cudaFuncAttributeMaxDynamicSharedMemorySize,
                             SMEM_MLP);
        cudaFuncSetAttribute(pcomp_kernel, cudaFuncAttributeMaxDynamicSharedMemorySize,
                             SMEM_PC);
        attr_set = true;
    }

    cudaMemsetAsync(d_out, 0, (size_t)out_size * sizeof(float));
    reset_kernel<<<(2 * NCAP + 1023) / 1024, 1024>>>();
    prep_kernel<<<320, 256>>>(W1o, W1i, W2o, W2i);
    hist_kernel<<<(E + 255) / 256, 256>>>(ei, E);
    scan_kernel<<<2, 1024>>>();
    scatter_kernel<<<(E + 255) / 256, 256>>>(ei, E);
    pcomp_kernel<<<dim3((N + 127) / 128, 2), NTH, SMEM_PC>>>(x, b1o, b1i, N);

    dim3 grid((E + TILE - 1) / TILE, 2);
    mlp_kernel<<<grid, NTH, SMEM_MLP>>>(ei, ea, b2o, b2i, E, out);
}

// round 10
// speedup vs baseline: 1.3852x; 1.3230x over previous
#include <cuda_runtime.h>
#include <cstdint>

#define TILE   128
#define NTH    256
#define MAX_E  800000
#define NCAP   50048

// ---- mlp kernel smem layout (bytes) ----
#define SM_ROWS 0          // int[128]
#define SM_COLS 512        // int[128]
#define SM_EIDX 1024       // int[128]
#define SM_B2   1536       // float[128]
#define SM_A    2048       // 128 rows x 144 B: 18432 -> ends 20480
#define SM_W1E  20480      // 256 rows x 144 B: 36864 -> ends 57344
#define SM_W2C  57344      // 2 chunks x (128 rows x 144 B) = 36864 -> ends 94208
#define SMEM_MLP 94208

// ---- pcomp kernel smem layout ----
#define PC_B1   0          // float[256]
#define PC_A    1024       // 128 rows x 272 B: 34816
#define PC_W    35840      // 256 rows x 272 B: 69632
#define SMEM_PC 105472

__device__ int g_cnt[2];
__device__ int g_list[2 * MAX_E];
// packed fp16 weight images in smem (ldmatrix) layout, incl. row pads
__device__ uint32_t gW1eh[2 * 256 * 36];    // [f][n<256][kpair<32 +pad]
__device__ uint32_t gW1xh[2 * 256 * 68];    // [f][n<256][kpair<64 +pad]
__device__ uint32_t gW2h [2 * 128 * 132];   // [f][n<128][kpair<128 +pad]
// P[f][node][q<4][j2<16][4] = x[node]@W1x_f + b1_f (fragment-permuted rows)
__device__ float g_P[2 * (size_t)NCAP * 256];

// ---------------- helpers ----------------
static __device__ __forceinline__ uint32_t smem_u32(const void* p) {
    uint32_t a;
    asm("{ .reg .u64 t; cvta.to.shared.u64 t, %1; cvt.u32.u64 %0, t; }"
        : "=r"(a) : "l"(p));
    return a;
}
static __device__ __forceinline__ uint32_t pack_h2(float lo, float hi) {
    uint32_t r;
    asm("cvt.rn.f16x2.f32 %0, %1, %2;" : "=r"(r) : "f"(hi), "f"(lo));
    return r;
}
static __device__ __forceinline__ void sts128(uint32_t a, uint32_t r0, uint32_t r1,
                                              uint32_t r2, uint32_t r3) {
    asm volatile("st.shared.v4.b32 [%0], {%1,%2,%3,%4};"
                 :: "r"(a), "r"(r0), "r"(r1), "r"(r2), "r"(r3) : "memory");
}
static __device__ __forceinline__ void ldsm_x4(uint32_t r[4], uint32_t addr) {
    asm volatile("ldmatrix.sync.aligned.m8n8.x4.shared.b16 {%0,%1,%2,%3}, [%4];"
                 : "=r"(r[0]), "=r"(r[1]), "=r"(r[2]), "=r"(r[3]) : "r"(addr));
}
static __device__ __forceinline__ void mma_f16(float d[4], const uint32_t a[4],
                                               const uint32_t b[2]) {
    asm("mma.sync.aligned.m16n8k16.row.col.f32.f16.f16.f32 "
        "{%0,%1,%2,%3}, {%4,%5,%6,%7}, {%8,%9}, {%0,%1,%2,%3};"
        : "+f"(d[0]), "+f"(d[1]), "+f"(d[2]), "+f"(d[3])
        : "r"(a[0]), "r"(a[1]), "r"(a[2]), "r"(a[3]), "r"(b[0]), "r"(b[1]));
}
static __device__ __forceinline__ void red_add2(float* p, float a, float b) {
    asm volatile("red.global.add.v2.f32 [%0], {%1,%2};"
                 :: "l"(p), "f"(a), "f"(b) : "memory");
}
static __device__ __forceinline__ void cpa16(uint32_t d, const uint32_t* s) {
    asm volatile("cp.async.ca.shared.global [%0], [%1], 16;"
                 :: "r"(d), "l"(s) : "memory");
}
#define CP_COMMIT() asm volatile("cp.async.commit_group;" ::: "memory")
#define CP_WAIT(n)  asm volatile("cp.async.wait_group %0;" :: "n"(n) : "memory")

// ---------------- setup kernels ----------------
// fp16 images: W1e 16384, W1x 32768, W2 32768 pack-pairs (+ counter reset)
__global__ void prep_kernel(const float* __restrict__ W1o, const float* __restrict__ W1i,
                            const float* __restrict__ W2o, const float* __restrict__ W2i) {
    int idx = blockIdx.x * 256 + threadIdx.x;
    if (idx < 2) g_cnt[idx] = 0;
    if (idx < 16384) {                          // W1e: [f][nl<256][p<32]
        int p = idx & 31; int t = idx >> 5;
        int nl = t & 255; int f = t >> 8;
        const float* W = f ? W1i : W1o;
        gW1eh[(f * 256 + nl) * 36 + p] =
            pack_h2(W[(128 + 2 * p) * 256 + nl], W[(129 + 2 * p) * 256 + nl]);
    } else if (idx < 49152) {                   // W1x: [f][nl<256][p<64]
        int i = idx - 16384;
        int p = i & 63; int t = i >> 6;
        int nl = t & 255; int f = t >> 8;
        const float* W = f ? W1i : W1o;
        gW1xh[(f * 256 + nl) * 68 + p] =
            pack_h2(W[(2 * p) * 256 + nl], W[(2 * p + 1) * 256 + nl]);
    } else if (idx < 81920) {                   // W2: [f][nl<128][p<128]
        int i = idx - 49152;
        int p = i & 127; int t = i >> 7;
        int nl = t & 127; int f = t >> 7;
        const float* W = f ? W2i : W2o;
        gW2h[(f * 128 + nl) * 132 + p] =
            pack_h2(W[(2 * p) * 128 + nl], W[(2 * p + 1) * 128 + nl]);
    }
}

__global__ void partition_kernel(const int* __restrict__ ei, int E) {
    __shared__ int s_cnt[2], s_base[2];
    int tid = threadIdx.x;
    if (tid < 2) s_cnt[tid] = 0;
    __syncthreads();
    int e = blockIdx.x * blockDim.x + tid;
    bool valid = e < E;
    int r = 0, c = 0;
    if (valid) { r = ei[e]; c = ei[E + e]; }
    int lane = tid & 31;
    bool po = valid && (r < c);
    bool pi = valid && (r > c);
    unsigned mo = __ballot_sync(0xffffffffu, po);
    unsigned mi = __ballot_sync(0xffffffffu, pi);
    int lo = __ffs(mo) - 1, li = __ffs(mi) - 1;
    int wo = 0, wi = 0;
    if (mo && lane == lo) wo = atomicAdd(&s_cnt[0], __popc(mo));
    if (mi && lane == li) wi = atomicAdd(&s_cnt[1], __popc(mi));
    __syncthreads();
    if (tid == 0) s_base[0] = atomicAdd(&g_cnt[0], s_cnt[0]);
    if (tid == 1) s_base[1] = atomicAdd(&g_cnt[1], s_cnt[1]);
    __syncthreads();
    if (mo) wo = __shfl_sync(0xffffffffu, wo, lo);
    if (mi) wi = __shfl_sync(0xffffffffu, wi, li);
    unsigned lt = (1u << lane) - 1u;
    if (po) g_list[s_base[0] + wo + __popc(mo & lt)] = e;
    if (pi) g_list[MAX_E + s_base[1] + wi + __popc(mi & lt)] = e;
}

// ---------------- P precompute: P = x @ W1x + b1 (per flavor) ----------------
__global__ __launch_bounds__(NTH, 1)
void pcomp_kernel(const float* __restrict__ x,
                  const float* __restrict__ b1o, const float* __restrict__ b1i,
                  int N) {
    int f = blockIdx.y;
    int base = blockIdx.x * 128;
    if (base >= N) return;
    const float* b1 = f ? b1i : b1o;

    extern __shared__ __align__(16) char smem[];
    uint32_t sb = smem_u32(smem);
    uint32_t sbA = sb + PC_A, sbW = sb + PC_W;
    int tid = threadIdx.x, wid = tid >> 5, lane = tid & 31;

    {
        const uint32_t* src = gW1xh + (size_t)f * 256 * 68;
        #pragma unroll
        for (int i = 0; i < 17; i++) {
            int s = tid + i * NTH;
            cpa16(sbW + s * 16, src + s * 4);
        }
        CP_COMMIT();
    }
    ((float*)(smem + PC_B1))[tid] = b1[tid];

    {
        int r = tid & 127, h = tid >> 7;
        int node = min(base + r, N - 1);
        const float4* xr = (const float4*)(x + (size_t)node * 128);
        #pragma unroll
        for (int q = 0; q < 8; q++) {
            float4 a = xr[h * 16 + 2 * q], b = xr[h * 16 + 2 * q + 1];
            sts128(sbA + r * 272 + h * 128 + q * 16,
                   pack_h2(a.x, a.y), pack_h2(a.z, a.w),
                   pack_h2(b.x, b.y), pack_h2(b.z, b.w));
        }
    }
    CP_WAIT(0);
    __syncthreads();

    uint32_t aB = sbA + (wid * 16 + (lane & 15)) * 272 + (lane >> 4) * 16;
    uint32_t bB = sbW + (uint32_t)((lane & 7) + ((lane >> 4) << 3)) * 272
                + (uint32_t)(((lane >> 3) & 1) << 4);

    float acc[32][4];
    #pragma unroll
    for (int j = 0; j < 32; j++)
        #pragma unroll
        for (int p = 0; p < 4; p++) acc[j][p] = 0.0f;

    for (int s = 0; s < 8; s++) {
        uint32_t af[4]; ldsm_x4(af, aB + s * 32);
        #pragma unroll
        for (int nt2 = 0; nt2 < 16; nt2++) {
            uint32_t bf4[4];
            ldsm_x4(bf4, bB + nt2 * 4352 + s * 32);
            mma_f16(acc[2 * nt2],     af, bf4);
            mma_f16(acc[2 * nt2 + 1], af, bf4 + 2);
        }
    }

    {
        const float* b1s = (const float*)(smem + PC_B1);
        int q = lane & 3, t2 = 2 * q;
        int m1 = wid * 16 + (lane >> 2), m2 = m1 + 8;
        int n1 = base + m1, n2 = base + m2;
        float* p1 = g_P + ((size_t)f * NCAP + n1) * 256 + q * 64;
        float* p2 = g_P + ((size_t)f * NCAP + n2) * 256 + q * 64;
        #pragma unroll
        for (int j = 0; j < 32; j += 2) {
            if (n1 < N) {
                float4 v = { acc[j][0]     + b1s[8 * j + t2],
                             acc[j][1]     + b1s[8 * j + t2 + 1],
                             acc[j + 1][0] + b1s[8 * (j + 1) + t2],
                             acc[j + 1][1] + b1s[8 * (j + 1) + t2 + 1] };
                *(float4*)(p1 + j * 2) = v;
            }
            if (n2 < N) {
                float4 v = { acc[j][2]     + b1s[8 * j + t2],
                             acc[j][3]     + b1s[8 * j + t2 + 1],
                             acc[j + 1][2] + b1s[8 * (j + 1) + t2],
                             acc[j + 1][3] + b1s[8 * (j + 1) + t2 + 1] };
                *(float4*)(p2 + j * 2) = v;
            }
        }
    }
}

// ---------------- W2 quarter-chunk copy (32 kpairs = 128 B per n-row) -------
static __device__ __forceinline__ void cp_w2_chunk(int f, int c, uint32_t dst, int tid) {
    const uint32_t* src = gW2h + (size_t)f * 128 * 132 + c * 32;
    #pragma unroll
    for (int i = 0; i < 4; i++) {
        int s = tid + i * NTH;          // s < 1024
        int nl = s >> 3, seg = s & 7;
        cpa16(dst + nl * 144 + seg * 16, src + (size_t)nl * 132 + seg * 4);
    }
}

// ---------------- main edge-MLP kernel (fused GEMM1->GEMM2, 2 CTAs/SM) -----
__global__ __launch_bounds__(NTH, 2)
void mlp_kernel(const int* __restrict__ ei, const float* __restrict__ ea,
                const float* __restrict__ b2o, const float* __restrict__ b2i,
                int E, float* __restrict__ out) {
    int f = blockIdx.y;
    int cnt = g_cnt[f];
    int base = blockIdx.x * TILE;
    if (base >= cnt) return;
    int nvalid = min(TILE, cnt - base);
    const int* list = g_list + f * MAX_E;
    int colOff = f ? 0 : 128;
    const float* b2 = f ? b2i : b2o;

    extern __shared__ __align__(16) char smem[];
    uint32_t sb = smem_u32(smem);
    uint32_t sbA = sb + SM_A;
    int tid = threadIdx.x, wid = tid >> 5, lane = tid & 31;
    int q = lane & 3;
    int m1 = wid * 16 + (lane >> 2), m2 = m1 + 8;

    // early direct loads of this thread's P row pointers (no smem dependency)
    int e1 = __ldg(list + base + min(m1, nvalid - 1));
    int e2 = __ldg(list + base + min(m2, nvalid - 1));
    int node1 = __ldg(ei + E + e1);
    int node2 = __ldg(ei + E + e2);
    const float4* p1 = (const float4*)(g_P + ((size_t)f * NCAP + node1) * 256 + q * 64);
    const float4* p2 = (const float4*)(g_P + ((size_t)f * NCAP + node2) * 256 + q * 64);

    // stream W1e (group 1): 2304 x 16B;  W2 chunks 0,1 (groups 2,3)
    {
        const uint32_t* src = gW1eh + (size_t)f * 256 * 36;
        #pragma unroll
        for (int i = 0; i < 9; i++) {
            int s = tid + i * NTH;
            cpa16(sb + SM_W1E + s * 16, src + s * 4);
        }
        CP_COMMIT();
    }
    cp_w2_chunk(f, 0, sb + SM_W2C, tid);          CP_COMMIT();
    cp_w2_chunk(f, 1, sb + SM_W2C + 18432, tid);  CP_COMMIT();

    // headers
    if (tid < TILE) {
        int e = list[base + min(tid, nvalid - 1)];
        ((int*)(smem + SM_EIDX))[tid] = e;
        ((int*)(smem + SM_ROWS))[tid] = ei[e];
    }
    if (tid < 128) ((float*)(smem + SM_B2))[tid] = b2[tid];
    __syncthreads();

    // ---- gather A = edge_attr as f16, stride 144 B ----
    {
        int r = tid & 127, h = tid >> 7;
        int eidx = ((const int*)(smem + SM_EIDX))[r];
        const float4* er = (const float4*)(ea + (size_t)eidx * 64);
        #pragma unroll
        for (int qq = 0; qq < 4; qq++) {
            float4 a = er[h * 8 + 2 * qq], b = er[h * 8 + 2 * qq + 1];
            sts128(sbA + r * 144 + h * 64 + qq * 16,
                   pack_h2(a.x, a.y), pack_h2(a.z, a.w),
                   pack_h2(b.x, b.y), pack_h2(b.z, b.w));
        }
    }
    CP_WAIT(2);          // W1e resident (W2 chunks may lag)
    __syncthreads();

    uint32_t aB = sbA + (wid * 16 + (lane & 15)) * 144 + (lane >> 4) * 16;
    uint32_t bo144 = (uint32_t)((lane & 7) + ((lane >> 4) << 3)) * 144
                   + (uint32_t)(((lane >> 3) & 1) << 4);

    // A-fragments for all 4 k16-steps of GEMM1 (reused every j2)
    uint32_t af1[4][4];
    #pragma unroll
    for (int s = 0; s < 4; s++) ldsm_x4(af1[s], aB + s * 32);

    float acc2[16][4];
    #pragma unroll
    for (int j = 0; j < 16; j++)
        #pragma unroll
        for (int p = 0; p < 4; p++) acc2[j][p] = 0.0f;

    uint32_t bW1 = sb + SM_W1E + bo144;

    // ---- fused loop: produce h n-tile pair j2, consume as GEMM2 k-step j2 --
    float4 pva = p1[0], pvb = p2[0];
    #pragma unroll
    for (int c = 0; c < 4; c++) {
        if (c < 3) CP_WAIT(1); else CP_WAIT(0);
        __syncthreads();
        uint32_t bW2 = sb + SM_W2C + (c & 1) * 18432 + bo144;
        #pragma unroll
        for (int ks = 0; ks < 4; ks++) {
            int j2 = c * 4 + ks;
            float4 nva, nvb;
            if (j2 < 15) { nva = p1[j2 + 1]; nvb = p2[j2 + 1]; }
            // acc1 tile pair init from P
            float a1[2][4] = { { pva.x, pva.y, pvb.x, pvb.y },
                               { pva.z, pva.w, pvb.z, pvb.w } };
            // GEMM1: += A_ea @ W1e for this n-tile pair
            #pragma unroll
            for (int s = 0; s < 4; s++) {
                uint32_t bf4[4];
                ldsm_x4(bf4, bW1 + j2 * 2304 + s * 32);
                mma_f16(a1[0], af1[s], bf4);
                mma_f16(a1[1], af1[s], bf4 + 2);
            }
            // relu + pack -> GEMM2 A-fragment
            uint32_t af[4];
            af[0] = pack_h2(fmaxf(a1[0][0], 0.f), fmaxf(a1[0][1], 0.f));
            af[1] = pack_h2(fmaxf(a1[0][2], 0.f), fmaxf(a1[0][3], 0.f));
            af[2] = pack_h2(fmaxf(a1[1][0], 0.f), fmaxf(a1[1][1], 0.f));
            af[3] = pack_h2(fmaxf(a1[1][2], 0.f), fmaxf(a1[1][3], 0.f));
            // GEMM2: k16-step ks of chunk c
            #pragma unroll
            for (int nt2 = 0; nt2 < 8; nt2++) {
                uint32_t bf4[4];
                ldsm_x4(bf4, bW2 + nt2 * 2304 + ks * 32);
                mma_f16(acc2[2 * nt2],     af, bf4);
                mma_f16(acc2[2 * nt2 + 1], af, bf4 + 2);
            }
            pva = nva; pvb = nvb;
        }
        __syncthreads();
        if (c < 2) { cp_w2_chunk(f, c + 2, sb + SM_W2C + (c & 1) * 18432, tid); CP_COMMIT(); }
    }

    // ---- epilogue: + b2, vectorized scatter-add ----
    {
        const float* b2s = (const float*)(smem + SM_B2);
        const int* rows = (const int*)(smem + SM_ROWS);
        bool ok1 = m1 < nvalid, ok2 = m2 < nvalid;
        float* o1 = ok1 ? (out + (size_t)rows[m1] * 256 + colOff) : out;
        float* o2 = ok2 ? (out + (size_t)rows[m2] * 256 + colOff) : out;
        int t2 = 2 * q;
        #pragma unroll
        for (int nt = 0; nt < 16; nt++) {
            int n0 = 8 * nt + t2;
            if (ok1) red_add2(o1 + n0, acc2[nt][0] + b2s[n0], acc2[nt][1] + b2s[n0 + 1]);
            if (ok2) red_add2(o2 + n0, acc2[nt][2] + b2s[n0], acc2[nt][3] + b2s[n0 + 1]);
        }
    }
}

// ---------------- host launch ----------------
extern "C" void kernel_launch(void* const* d_in, const int* in_sizes, int n_in,
                              void* d_out, int out_size) {
    const float* x   = (const float*)d_in[0];
    const int*   ei  = (const int*)  d_in[1];
    const float* ea  = (const float*)d_in[2];
    const float* W1o = (const float*)d_in[3];
    const float* b1o = (const float*)d_in[4];
    const float* W2o = (const float*)d_in[5];
    const float* b2o = (const float*)d_in[6];
    const float* W1i = (const float*)d_in[7];
    const float* b1i = (const float*)d_in[8];
    const float* W2i = (const float*)d_in[9];
    const float* b2i = (const float*)d_in[10];
    float* out = (float*)d_out;
    int E = in_sizes[1] / 2;
    int N = in_sizes[0] / 128;
    if (N > NCAP) N = NCAP;

    static bool attr_set = false;
    if (!attr_set) {
        cudaFuncSetAttribute(mlp_kernel, cudaFuncAttributeMaxDynamicSharedMemorySize,
                             SMEM_MLP);
        cudaFuncSetAttribute(pcomp_kernel, cudaFuncAttributeMaxDynamicSharedMemorySize,
                             SMEM_PC);
        attr_set = true;
    }

    cudaMemsetAsync(d_out, 0, (size_t)out_size * sizeof(float));
    prep_kernel<<<320, 256>>>(W1o, W1i, W2o, W2i);   // also resets g_cnt
    partition_kernel<<<(E + 511) / 512, 512>>>(ei, E);
    pcomp_kernel<<<dim3((N + 127) / 128, 2), NTH, SMEM_PC>>>(x, b1o, b1i, N);

    dim3 grid((E + TILE - 1) / TILE, 2);
    mlp_kernel<<<grid, NTH, SMEM_MLP>>>(ei, ea, b2o, b2i, E, out);
}

// round 11
// speedup vs baseline: 1.5188x; 1.0965x over previous
#include <cuda_runtime.h>
#include <cstdint>

#define TILE   128
#define NTH    128
#define MAX_E  800000
#define NCAP   50048

// ---- mlp kernel smem layout (bytes) ----
#define SM_ROWS 0          // int[128]
#define SM_EIDX 512        // int[128]
#define SM_B2   1024       // float[128]
#define SM_A    1536       // 128 rows x 144 B: 18432 -> ends 19968
#define SM_W1E  19968      // 256 rows x 144 B: 36864 -> ends 56832
#define SM_W2C  56832      // 2 chunks x (128 rows x 144 B) = 36864 -> ends 93696
#define SMEM_MLP 93696

// ---- pcomp kernel smem layout ----
#define PC_B1   0          // float[256]
#define PC_A    1024       // 128 rows x 272 B: 34816
#define PC_W    35840      // 256 rows x 272 B: 69632
#define SMEM_PC 105472

__device__ int g_cnt[2];
__device__ int g_list[2 * MAX_E];
// packed fp16 weight images in smem (ldmatrix) layout, incl. row pads
__device__ uint32_t gW1eh[2 * 256 * 36];    // [f][n<256][kpair<32 +pad]
__device__ uint32_t gW1xh[2 * 256 * 68];    // [f][n<256][kpair<64 +pad]
__device__ uint32_t gW2h [2 * 128 * 132];   // [f][n<128][kpair<128 +pad]
// P[f][node][q<4][j2<16][4] = x[node]@W1x_f + b1_f (fragment-permuted rows)
__device__ float g_P[2 * (size_t)NCAP * 256];

// ---------------- helpers ----------------
static __device__ __forceinline__ uint32_t smem_u32(const void* p) {
    uint32_t a;
    asm("{ .reg .u64 t; cvta.to.shared.u64 t, %1; cvt.u32.u64 %0, t; }"
        : "=r"(a) : "l"(p));
    return a;
}
static __device__ __forceinline__ uint32_t pack_h2(float lo, float hi) {
    uint32_t r;
    asm("cvt.rn.f16x2.f32 %0, %1, %2;" : "=r"(r) : "f"(hi), "f"(lo));
    return r;
}
static __device__ __forceinline__ void sts128(uint32_t a, uint32_t r0, uint32_t r1,
                                              uint32_t r2, uint32_t r3) {
    asm volatile("st.shared.v4.b32 [%0], {%1,%2,%3,%4};"
                 :: "r"(a), "r"(r0), "r"(r1), "r"(r2), "r"(r3) : "memory");
}
static __device__ __forceinline__ void ldsm_x4(uint32_t r[4], uint32_t addr) {
    asm volatile("ldmatrix.sync.aligned.m8n8.x4.shared.b16 {%0,%1,%2,%3}, [%4];"
                 : "=r"(r[0]), "=r"(r[1]), "=r"(r[2]), "=r"(r[3]) : "r"(addr));
}
static __device__ __forceinline__ void mma_f16(float d[4], const uint32_t a[4],
                                               const uint32_t b[2]) {
    asm("mma.sync.aligned.m16n8k16.row.col.f32.f16.f16.f32 "
        "{%0,%1,%2,%3}, {%4,%5,%6,%7}, {%8,%9}, {%0,%1,%2,%3};"
        : "+f"(d[0]), "+f"(d[1]), "+f"(d[2]), "+f"(d[3])
        : "r"(a[0]), "r"(a[1]), "r"(a[2]), "r"(a[3]), "r"(b[0]), "r"(b[1]));
}
static __device__ __forceinline__ void red_add2(float* p, float a, float b) {
    asm volatile("red.global.add.v2.f32 [%0], {%1,%2};"
                 :: "l"(p), "f"(a), "f"(b) : "memory");
}
static __device__ __forceinline__ void cpa16(uint32_t d, const uint32_t* s) {
    asm volatile("cp.async.ca.shared.global [%0], [%1], 16;"
                 :: "r"(d), "l"(s) : "memory");
}
#define CP_COMMIT() asm volatile("cp.async.commit_group;" ::: "memory")
#define CP_WAIT(n)  asm volatile("cp.async.wait_group %0;" :: "n"(n) : "memory")

// ---------------- setup kernels ----------------
__global__ void prep_kernel(const float* __restrict__ W1o, const float* __restrict__ W1i,
                            const float* __restrict__ W2o, const float* __restrict__ W2i) {
    int idx = blockIdx.x * 256 + threadIdx.x;
    if (idx < 2) g_cnt[idx] = 0;
    if (idx < 16384) {                          // W1e: [f][nl<256][p<32]
        int p = idx & 31; int t = idx >> 5;
        int nl = t & 255; int f = t >> 8;
        const float* W = f ? W1i : W1o;
        gW1eh[(f * 256 + nl) * 36 + p] =
            pack_h2(W[(128 + 2 * p) * 256 + nl], W[(129 + 2 * p) * 256 + nl]);
    } else if (idx < 49152) {                   // W1x: [f][nl<256][p<64]
        int i = idx - 16384;
        int p = i & 63; int t = i >> 6;
        int nl = t & 255; int f = t >> 8;
        const float* W = f ? W1i : W1o;
        gW1xh[(f * 256 + nl) * 68 + p] =
            pack_h2(W[(2 * p) * 256 + nl], W[(2 * p + 1) * 256 + nl]);
    } else if (idx < 81920) {                   // W2: [f][nl<128][p<128]
        int i = idx - 49152;
        int p = i & 127; int t = i >> 7;
        int nl = t & 127; int f = t >> 7;
        const float* W = f ? W2i : W2o;
        gW2h[(f * 128 + nl) * 132 + p] =
            pack_h2(W[(2 * p) * 128 + nl], W[(2 * p + 1) * 128 + nl]);
    }
}

__global__ void partition_kernel(const int* __restrict__ ei, int E) {
    __shared__ int s_cnt[2], s_base[2];
    int tid = threadIdx.x;
    if (tid < 2) s_cnt[tid] = 0;
    __syncthreads();
    int e = blockIdx.x * blockDim.x + tid;
    bool valid = e < E;
    int r = 0, c = 0;
    if (valid) { r = ei[e]; c = ei[E + e]; }
    int lane = tid & 31;
    bool po = valid && (r < c);
    bool pi = valid && (r > c);
    unsigned mo = __ballot_sync(0xffffffffu, po);
    unsigned mi = __ballot_sync(0xffffffffu, pi);
    int lo = __ffs(mo) - 1, li = __ffs(mi) - 1;
    int wo = 0, wi = 0;
    if (mo && lane == lo) wo = atomicAdd(&s_cnt[0], __popc(mo));
    if (mi && lane == li) wi = atomicAdd(&s_cnt[1], __popc(mi));
    __syncthreads();
    if (tid == 0) s_base[0] = atomicAdd(&g_cnt[0], s_cnt[0]);
    if (tid == 1) s_base[1] = atomicAdd(&g_cnt[1], s_cnt[1]);
    __syncthreads();
    if (mo) wo = __shfl_sync(0xffffffffu, wo, lo);
    if (mi) wi = __shfl_sync(0xffffffffu, wi, li);
    unsigned lt = (1u << lane) - 1u;
    if (po) g_list[s_base[0] + wo + __popc(mo & lt)] = e;
    if (pi) g_list[MAX_E + s_base[1] + wi + __popc(mi & lt)] = e;
}

// ---------------- P precompute: P = x @ W1x + b1 (per flavor) ----------------
__global__ __launch_bounds__(256, 1)
void pcomp_kernel(const float* __restrict__ x,
                  const float* __restrict__ b1o, const float* __restrict__ b1i,
                  int N) {
    int f = blockIdx.y;
    int base = blockIdx.x * 128;
    if (base >= N) return;
    const float* b1 = f ? b1i : b1o;

    extern __shared__ __align__(16) char smem[];
    uint32_t sb = smem_u32(smem);
    uint32_t sbA = sb + PC_A, sbW = sb + PC_W;
    int tid = threadIdx.x, wid = tid >> 5, lane = tid & 31;

    {
        const uint32_t* src = gW1xh + (size_t)f * 256 * 68;
        #pragma unroll
        for (int i = 0; i < 17; i++) {
            int s = tid + i * 256;
            cpa16(sbW + s * 16, src + s * 4);
        }
        CP_COMMIT();
    }
    ((float*)(smem + PC_B1))[tid] = b1[tid];

    {
        int r = tid & 127, h = tid >> 7;
        int node = min(base + r, N - 1);
        const float4* xr = (const float4*)(x + (size_t)node * 128);
        #pragma unroll
        for (int q = 0; q < 8; q++) {
            float4 a = xr[h * 16 + 2 * q], b = xr[h * 16 + 2 * q + 1];
            sts128(sbA + r * 272 + h * 128 + q * 16,
                   pack_h2(a.x, a.y), pack_h2(a.z, a.w),
                   pack_h2(b.x, b.y), pack_h2(b.z, b.w));
        }
    }
    CP_WAIT(0);
    __syncthreads();

    uint32_t aB = sbA + (wid * 16 + (lane & 15)) * 272 + (lane >> 4) * 16;
    uint32_t bB = sbW + (uint32_t)((lane & 7) + ((lane >> 4) << 3)) * 272
                + (uint32_t)(((lane >> 3) & 1) << 4);

    float acc[32][4];
    #pragma unroll
    for (int j = 0; j < 32; j++)
        #pragma unroll
        for (int p = 0; p < 4; p++) acc[j][p] = 0.0f;

    for (int s = 0; s < 8; s++) {
        uint32_t af[4]; ldsm_x4(af, aB + s * 32);
        #pragma unroll
        for (int nt2 = 0; nt2 < 16; nt2++) {
            uint32_t bf4[4];
            ldsm_x4(bf4, bB + nt2 * 4352 + s * 32);
            mma_f16(acc[2 * nt2],     af, bf4);
            mma_f16(acc[2 * nt2 + 1], af, bf4 + 2);
        }
    }

    {
        const float* b1s = (const float*)(smem + PC_B1);
        int q = lane & 3, t2 = 2 * q;
        int m1 = wid * 16 + (lane >> 2), m2 = m1 + 8;
        int n1 = base + m1, n2 = base + m2;
        float* p1 = g_P + ((size_t)f * NCAP + n1) * 256 + q * 64;
        float* p2 = g_P + ((size_t)f * NCAP + n2) * 256 + q * 64;
        #pragma unroll
        for (int j = 0; j < 32; j += 2) {
            if (n1 < N) {
                float4 v = { acc[j][0]     + b1s[8 * j + t2],
                             acc[j][1]     + b1s[8 * j + t2 + 1],
                             acc[j + 1][0] + b1s[8 * (j + 1) + t2],
                             acc[j + 1][1] + b1s[8 * (j + 1) + t2 + 1] };
                *(float4*)(p1 + j * 2) = v;
            }
            if (n2 < N) {
                float4 v = { acc[j][2]     + b1s[8 * j + t2],
                             acc[j][3]     + b1s[8 * j + t2 + 1],
                             acc[j + 1][2] + b1s[8 * (j + 1) + t2],
                             acc[j + 1][3] + b1s[8 * (j + 1) + t2 + 1] };
                *(float4*)(p2 + j * 2) = v;
            }
        }
    }
}

// ---------------- W2 quarter-chunk copy (32 kpairs = 128 B per n-row) -------
static __device__ __forceinline__ void cp_w2_chunk(int f, int c, uint32_t dst, int tid) {
    const uint32_t* src = gW2h + (size_t)f * 128 * 132 + c * 32;
    #pragma unroll
    for (int i = 0; i < 8; i++) {
        int s = tid + i * NTH;          // s < 1024
        int nl = s >> 3, seg = s & 7;
        cpa16(dst + nl * 144 + seg * 16, src + (size_t)nl * 132 + seg * 4);
    }
}

// ---------------- main edge-MLP kernel (4 warps, m=32/warp, 2 CTAs/SM) -----
__global__ __launch_bounds__(NTH, 2)
void mlp_kernel(const int* __restrict__ ei, const float* __restrict__ ea,
                const float* __restrict__ b2o, const float* __restrict__ b2i,
                int E, float* __restrict__ out) {
    int f = blockIdx.y;
    int cnt = g_cnt[f];
    int base = blockIdx.x * TILE;
    if (base >= cnt) return;
    int nvalid = min(TILE, cnt - base);
    const int* list = g_list + f * MAX_E;
    int colOff = f ? 0 : 128;
    const float* b2 = f ? b2i : b2o;

    extern __shared__ __align__(16) char smem[];
    uint32_t sb = smem_u32(smem);
    uint32_t sbA = sb + SM_A;
    int tid = threadIdx.x, wid = tid >> 5, lane = tid & 31;
    int q = lane & 3;
    // 4 m-rows per thread: two m16 tiles at wid*32 and wid*32+16
    int m1 = wid * 32 + (lane >> 2);
    int m2 = m1 + 8, m3 = m1 + 16, m4 = m1 + 24;

    // P row pointers (direct global loads, no smem dependency)
    const float4* pp[4];
    {
        int mm[4] = { m1, m2, m3, m4 };
        #pragma unroll
        for (int t = 0; t < 4; t++) {
            int e = __ldg(list + base + min(mm[t], nvalid - 1));
            int node = __ldg(ei + E + e);
            pp[t] = (const float4*)(g_P + ((size_t)f * NCAP + node) * 256 + q * 64);
        }
    }

    // stream W1e (group 1): 2304 x 16B;  W2 chunks 0,1 (groups 2,3)
    {
        const uint32_t* src = gW1eh + (size_t)f * 256 * 36;
        #pragma unroll
        for (int i = 0; i < 18; i++) {
            int s = tid + i * NTH;
            cpa16(sb + SM_W1E + s * 16, src + s * 4);
        }
        CP_COMMIT();
    }
    cp_w2_chunk(f, 0, sb + SM_W2C, tid);          CP_COMMIT();
    cp_w2_chunk(f, 1, sb + SM_W2C + 18432, tid);  CP_COMMIT();

    // headers
    {
        int e = list[base + min(tid, nvalid - 1)];
        ((int*)(smem + SM_EIDX))[tid] = e;
        ((int*)(smem + SM_ROWS))[tid] = ei[e];
        ((float*)(smem + SM_B2))[tid] = b2[tid];
    }
    __syncthreads();

    // ---- gather A = edge_attr as f16, one full row per thread ----
    {
        int eidx = ((const int*)(smem + SM_EIDX))[tid];
        const float4* er = (const float4*)(ea + (size_t)eidx * 64);
        #pragma unroll
        for (int qq = 0; qq < 8; qq++) {
            float4 a = er[2 * qq], b = er[2 * qq + 1];
            sts128(sbA + tid * 144 + qq * 16,
                   pack_h2(a.x, a.y), pack_h2(a.z, a.w),
                   pack_h2(b.x, b.y), pack_h2(b.z, b.w));
        }
    }
    CP_WAIT(2);          // W1e resident
    __syncthreads();

    uint32_t bo144 = (uint32_t)((lane & 7) + ((lane >> 4) << 3)) * 144
                   + (uint32_t)(((lane >> 3) & 1) << 4);

    // A-fragments for both m16 tiles, all 4 k16-steps (held in regs)
    uint32_t af1[2][4][4];
    #pragma unroll
    for (int t = 0; t < 2; t++) {
        uint32_t aB = sbA + (wid * 32 + t * 16 + (lane & 15)) * 144 + (lane >> 4) * 16;
        #pragma unroll
        for (int s = 0; s < 4; s++) ldsm_x4(af1[t][s], aB + s * 32);
    }

    float acc2[2][16][4];
    #pragma unroll
    for (int t = 0; t < 2; t++)
        #pragma unroll
        for (int j = 0; j < 16; j++)
            #pragma unroll
            for (int p = 0; p < 4; p++) acc2[t][j][p] = 0.0f;

    uint32_t bW1 = sb + SM_W1E + bo144;

    // ---- fused loop: produce h n-tile pair j2 for both m-tiles, consume ----
    float4 pv[4];
    #pragma unroll
    for (int t = 0; t < 4; t++) pv[t] = pp[t][0];

    #pragma unroll
    for (int c = 0; c < 4; c++) {
        if (c < 3) CP_WAIT(1); else CP_WAIT(0);
        __syncthreads();
        uint32_t bW2 = sb + SM_W2C + (c & 1) * 18432 + bo144;
        #pragma unroll
        for (int ks = 0; ks < 4; ks++) {
            int j2 = c * 4 + ks;
            float4 nv[4];
            if (j2 < 15) {
                #pragma unroll
                for (int t = 0; t < 4; t++) nv[t] = pp[t][j2 + 1];
            }
            // acc1 init from P (tile0: rows m1,m2 ; tile1: rows m3,m4)
            float a1[2][2][4] = {
                { { pv[0].x, pv[0].y, pv[1].x, pv[1].y },
                  { pv[0].z, pv[0].w, pv[1].z, pv[1].w } },
                { { pv[2].x, pv[2].y, pv[3].x, pv[3].y },
                  { pv[2].z, pv[2].w, pv[3].z, pv[3].w } } };
            // GEMM1: B fragment shared across both m-tiles
            #pragma unroll
            for (int s = 0; s < 4; s++) {
                uint32_t bf4[4];
                ldsm_x4(bf4, bW1 + j2 * 2304 + s * 32);
                #pragma unroll
                for (int t = 0; t < 2; t++) {
                    mma_f16(a1[t][0], af1[t][s], bf4);
                    mma_f16(a1[t][1], af1[t][s], bf4 + 2);
                }
            }
            // relu + pack -> GEMM2 A-fragments
            uint32_t af[2][4];
            #pragma unroll
            for (int t = 0; t < 2; t++) {
                af[t][0] = pack_h2(fmaxf(a1[t][0][0], 0.f), fmaxf(a1[t][0][1], 0.f));
                af[t][1] = pack_h2(fmaxf(a1[t][0][2], 0.f), fmaxf(a1[t][0][3], 0.f));
                af[t][2] = pack_h2(fmaxf(a1[t][1][0], 0.f), fmaxf(a1[t][1][1], 0.f));
                af[t][3] = pack_h2(fmaxf(a1[t][1][2], 0.f), fmaxf(a1[t][1][3], 0.f));
            }
            // GEMM2: B fragment shared across both m-tiles
            #pragma unroll
            for (int nt2 = 0; nt2 < 8; nt2++) {
                uint32_t bf4[4];
                ldsm_x4(bf4, bW2 + nt2 * 2304 + ks * 32);
                #pragma unroll
                for (int t = 0; t < 2; t++) {
                    mma_f16(acc2[t][2 * nt2],     af[t], bf4);
                    mma_f16(acc2[t][2 * nt2 + 1], af[t], bf4 + 2);
                }
            }
            #pragma unroll
            for (int t = 0; t < 4; t++) pv[t] = nv[t];
        }
        __syncthreads();
        if (c < 2) { cp_w2_chunk(f, c + 2, sb + SM_W2C + (c & 1) * 18432, tid); CP_COMMIT(); }
    }

    // ---- epilogue: + b2, vectorized scatter-add (4 m-rows per thread) ----
    {
        const float* b2s = (const float*)(smem + SM_B2);
        const int* rows = (const int*)(smem + SM_ROWS);
        int mm[4] = { m1, m2, m3, m4 };
        int t2 = 2 * q;
        #pragma unroll
        for (int t = 0; t < 4; t++) {
            bool ok = mm[t] < nvalid;
            if (!ok) continue;
            float* o = out + (size_t)rows[mm[t]] * 256 + colOff;
            int ti = t >> 1, hi = (t & 1) ? 2 : 0;
            #pragma unroll
            for (int nt = 0; nt < 16; nt++) {
                int n0 = 8 * nt + t2;
                red_add2(o + n0, acc2[ti][nt][hi] + b2s[n0],
                                 acc2[ti][nt][hi + 1] + b2s[n0 + 1]);
            }
        }
    }
}

// ---------------- host launch ----------------
extern "C" void kernel_launch(void* const* d_in, const int* in_sizes, int n_in,
                              void* d_out, int out_size) {
    const float* x   = (const float*)d_in[0];
    const int*   ei  = (const int*)  d_in[1];
    const float* ea  = (const float*)d_in[2];
    const float* W1o = (const float*)d_in[3];
    const float* b1o = (const float*)d_in[4];
    const float* W2o = (const float*)d_in[5];
    const float* b2o = (const float*)d_in[6];
    const float* W1i = (const float*)d_in[7];
    const float* b1i = (const float*)d_in[8];
    const float* W2i = (const float*)d_in[9];
    const float* b2i = (const float*)d_in[10];
    float* out = (float*)d_out;
    int E = in_sizes[1] / 2;
    int N = in_sizes[0] / 128;
    if (N > NCAP) N = NCAP;

    static bool attr_set = false;
    if (!attr_set) {
        cudaFuncSetAttribute(mlp_kernel, cudaFuncAttributeMaxDynamicSharedMemorySize,
                             SMEM_MLP);
        cudaFuncSetAttribute(pcomp_kernel, cudaFuncAttributeMaxDynamicSharedMemorySize,
                             SMEM_PC);
        attr_set = true;
    }

    cudaMemsetAsync(d_out, 0, (size_t)out_size * sizeof(float));
    prep_kernel<<<320, 256>>>(W1o, W1i, W2o, W2i);   // also resets g_cnt
    partition_kernel<<<(E + 511) / 512, 512>>>(ei, E);
    pcomp_kernel<<<dim3((N + 127) / 128, 2), 256, SMEM_PC>>>(x, b1o, b1i, N);

    dim3 grid((E + TILE - 1) / TILE, 2);
    mlp_kernel<<<grid, NTH, SMEM_MLP>>>(ei, ea, b2o, b2i, E, out);
}

// round 12
// speedup vs baseline: 1.5244x; 1.0037x over previous
#include <cuda_runtime.h>
#include <cstdint>

#define TILE   128
#define NTH    128
#define MAX_E  800000
#define NCAP   50048

// ---- mlp kernel smem layout (bytes) ----
#define SM_ROWS 0          // int[128]
#define SM_EIDX 512        // int[128]
#define SM_B2   1024       // float[128]
#define SM_A    1536       // 128 rows x 144 B: 18432 -> ends 19968
#define SM_W1E  19968      // 256 rows x 144 B: 36864 -> ends 56832
#define SM_W2C  56832      // 2 chunks x (128 rows x 144 B) = 36864 -> ends 93696
#define SMEM_MLP 93696

// ---- pcomp kernel smem layout ----
#define PC_B1   0          // float[256]
#define PC_A    1024       // 128 rows x 272 B: 34816
#define PC_W    35840      // 256 rows x 272 B: 69632
#define SMEM_PC 105472

__device__ int g_cnt[2];
__device__ int g_list[2 * MAX_E];
// packed fp16 weight images in smem (ldmatrix) layout, incl. row pads
__device__ uint32_t gW1eh[2 * 256 * 36];    // [f][n<256][kpair<32 +pad]
__device__ uint32_t gW1xh[2 * 256 * 68];    // [f][n<256][kpair<64 +pad]
__device__ uint32_t gW2h [2 * 128 * 132];   // [f][n<128][kpair<128 +pad]
// P[f][node][q<4][j2<16][4] = x[node]@W1x_f + b1_f (fragment-permuted rows)
__device__ float g_P[2 * (size_t)NCAP * 256];

// ---------------- helpers ----------------
static __device__ __forceinline__ uint32_t smem_u32(const void* p) {
    uint32_t a;
    asm("{ .reg .u64 t; cvta.to.shared.u64 t, %1; cvt.u32.u64 %0, t; }"
        : "=r"(a) : "l"(p));
    return a;
}
static __device__ __forceinline__ uint32_t pack_h2(float lo, float hi) {
    uint32_t r;
    asm("cvt.rn.f16x2.f32 %0, %1, %2;" : "=r"(r) : "f"(hi), "f"(lo));
    return r;
}
static __device__ __forceinline__ void sts128(uint32_t a, uint32_t r0, uint32_t r1,
                                              uint32_t r2, uint32_t r3) {
    asm volatile("st.shared.v4.b32 [%0], {%1,%2,%3,%4};"
                 :: "r"(a), "r"(r0), "r"(r1), "r"(r2), "r"(r3) : "memory");
}
static __device__ __forceinline__ void ldsm_x4(uint32_t r[4], uint32_t addr) {
    asm volatile("ldmatrix.sync.aligned.m8n8.x4.shared.b16 {%0,%1,%2,%3}, [%4];"
                 : "=r"(r[0]), "=r"(r[1]), "=r"(r[2]), "=r"(r[3]) : "r"(addr));
}
static __device__ __forceinline__ void mma_f16(float d[4], const uint32_t a[4],
                                               const uint32_t b[2]) {
    asm("mma.sync.aligned.m16n8k16.row.col.f32.f16.f16.f32 "
        "{%0,%1,%2,%3}, {%4,%5,%6,%7}, {%8,%9}, {%0,%1,%2,%3};"
        : "+f"(d[0]), "+f"(d[1]), "+f"(d[2]), "+f"(d[3])
        : "r"(a[0]), "r"(a[1]), "r"(a[2]), "r"(a[3]), "r"(b[0]), "r"(b[1]));
}
static __device__ __forceinline__ void red_add2(float* p, float a, float b) {
    asm volatile("red.global.add.v2.f32 [%0], {%1,%2};"
                 :: "l"(p), "f"(a), "f"(b) : "memory");
}
static __device__ __forceinline__ void cpa16(uint32_t d, const uint32_t* s) {
    asm volatile("cp.async.ca.shared.global [%0], [%1], 16;"
                 :: "r"(d), "l"(s) : "memory");
}
#define CP_COMMIT() asm volatile("cp.async.commit_group;" ::: "memory")
#define CP_WAIT(n)  asm volatile("cp.async.wait_group %0;" :: "n"(n) : "memory")

// ---------------- setup kernels ----------------
__global__ void prep_kernel(const float* __restrict__ W1o, const float* __restrict__ W1i,
                            const float* __restrict__ W2o, const float* __restrict__ W2i) {
    int idx = blockIdx.x * 256 + threadIdx.x;
    if (idx < 2) g_cnt[idx] = 0;
    if (idx < 16384) {                          // W1e: [f][nl<256][p<32]
        int p = idx & 31; int t = idx >> 5;
        int nl = t & 255; int f = t >> 8;
        const float* W = f ? W1i : W1o;
        gW1eh[(f * 256 + nl) * 36 + p] =
            pack_h2(W[(128 + 2 * p) * 256 + nl], W[(129 + 2 * p) * 256 + nl]);
    } else if (idx < 49152) {                   // W1x: [f][nl<256][p<64]
        int i = idx - 16384;
        int p = i & 63; int t = i >> 6;
        int nl = t & 255; int f = t >> 8;
        const float* W = f ? W1i : W1o;
        gW1xh[(f * 256 + nl) * 68 + p] =
            pack_h2(W[(2 * p) * 256 + nl], W[(2 * p + 1) * 256 + nl]);
    } else if (idx < 81920) {                   // W2: [f][nl<128][p<128]
        int i = idx - 49152;
        int p = i & 127; int t = i >> 7;
        int nl = t & 127; int f = t >> 7;
        const float* W = f ? W2i : W2o;
        gW2h[(f * 128 + nl) * 132 + p] =
            pack_h2(W[(2 * p) * 128 + nl], W[(2 * p + 1) * 128 + nl]);
    }
}

__global__ void partition_kernel(const int* __restrict__ ei, int E) {
    __shared__ int s_cnt[2], s_base[2];
    int tid = threadIdx.x;
    if (tid < 2) s_cnt[tid] = 0;
    __syncthreads();
    int e = blockIdx.x * blockDim.x + tid;
    bool valid = e < E;
    int r = 0, c = 0;
    if (valid) { r = ei[e]; c = ei[E + e]; }
    int lane = tid & 31;
    bool po = valid && (r < c);
    bool pi = valid && (r > c);
    unsigned mo = __ballot_sync(0xffffffffu, po);
    unsigned mi = __ballot_sync(0xffffffffu, pi);
    int lo = __ffs(mo) - 1, li = __ffs(mi) - 1;
    int wo = 0, wi = 0;
    if (mo && lane == lo) wo = atomicAdd(&s_cnt[0], __popc(mo));
    if (mi && lane == li) wi = atomicAdd(&s_cnt[1], __popc(mi));
    __syncthreads();
    if (tid == 0) s_base[0] = atomicAdd(&g_cnt[0], s_cnt[0]);
    if (tid == 1) s_base[1] = atomicAdd(&g_cnt[1], s_cnt[1]);
    __syncthreads();
    if (mo) wo = __shfl_sync(0xffffffffu, wo, lo);
    if (mi) wi = __shfl_sync(0xffffffffu, wi, li);
    unsigned lt = (1u << lane) - 1u;
    if (po) g_list[s_base[0] + wo + __popc(mo & lt)] = e;
    if (pi) g_list[MAX_E + s_base[1] + wi + __popc(mi & lt)] = e;
}

// ---------------- P precompute: P = x @ W1x + b1 (per flavor) ----------------
__global__ __launch_bounds__(256, 1)
void pcomp_kernel(const float* __restrict__ x,
                  const float* __restrict__ b1o, const float* __restrict__ b1i,
                  int N) {
    int f = blockIdx.y;
    int base = blockIdx.x * 128;
    if (base >= N) return;
    const float* b1 = f ? b1i : b1o;

    extern __shared__ __align__(16) char smem[];
    uint32_t sb = smem_u32(smem);
    uint32_t sbA = sb + PC_A, sbW = sb + PC_W;
    int tid = threadIdx.x, wid = tid >> 5, lane = tid & 31;

    {
        const uint32_t* src = gW1xh + (size_t)f * 256 * 68;
        #pragma unroll
        for (int i = 0; i < 17; i++) {
            int s = tid + i * 256;
            cpa16(sbW + s * 16, src + s * 4);
        }
        CP_COMMIT();
    }
    ((float*)(smem + PC_B1))[tid] = b1[tid];

    {
        int r = tid & 127, h = tid >> 7;
        int node = min(base + r, N - 1);
        const float4* xr = (const float4*)(x + (size_t)node * 128);
        #pragma unroll
        for (int q = 0; q < 8; q++) {
            float4 a = xr[h * 16 + 2 * q], b = xr[h * 16 + 2 * q + 1];
            sts128(sbA + r * 272 + h * 128 + q * 16,
                   pack_h2(a.x, a.y), pack_h2(a.z, a.w),
                   pack_h2(b.x, b.y), pack_h2(b.z, b.w));
        }
    }
    CP_WAIT(0);
    __syncthreads();

    uint32_t aB = sbA + (wid * 16 + (lane & 15)) * 272 + (lane >> 4) * 16;
    uint32_t bB = sbW + (uint32_t)((lane & 7) + ((lane >> 4) << 3)) * 272
                + (uint32_t)(((lane >> 3) & 1) << 4);

    float acc[32][4];
    #pragma unroll
    for (int j = 0; j < 32; j++)
        #pragma unroll
        for (int p = 0; p < 4; p++) acc[j][p] = 0.0f;

    for (int s = 0; s < 8; s++) {
        uint32_t af[4]; ldsm_x4(af, aB + s * 32);
        #pragma unroll
        for (int nt2 = 0; nt2 < 16; nt2++) {
            uint32_t bf4[4];
            ldsm_x4(bf4, bB + nt2 * 4352 + s * 32);
            mma_f16(acc[2 * nt2],     af, bf4);
            mma_f16(acc[2 * nt2 + 1], af, bf4 + 2);
        }
    }

    {
        const float* b1s = (const float*)(smem + PC_B1);
        int q = lane & 3, t2 = 2 * q;
        int m1 = wid * 16 + (lane >> 2), m2 = m1 + 8;
        int n1 = base + m1, n2 = base + m2;
        float* p1 = g_P + ((size_t)f * NCAP + n1) * 256 + q * 64;
        float* p2 = g_P + ((size_t)f * NCAP + n2) * 256 + q * 64;
        #pragma unroll
        for (int j = 0; j < 32; j += 2) {
            if (n1 < N) {
                float4 v = { acc[j][0]     + b1s[8 * j + t2],
                             acc[j][1]     + b1s[8 * j + t2 + 1],
                             acc[j + 1][0] + b1s[8 * (j + 1) + t2],
                             acc[j + 1][1] + b1s[8 * (j + 1) + t2 + 1] };
                *(float4*)(p1 + j * 2) = v;
            }
            if (n2 < N) {
                float4 v = { acc[j][2]     + b1s[8 * j + t2],
                             acc[j][3]     + b1s[8 * j + t2 + 1],
                             acc[j + 1][2] + b1s[8 * (j + 1) + t2],
                             acc[j + 1][3] + b1s[8 * (j + 1) + t2 + 1] };
                *(float4*)(p2 + j * 2) = v;
            }
        }
    }
}

// ---------------- W2 quarter-chunk copy (32 kpairs = 128 B per n-row) -------
static __device__ __forceinline__ void cp_w2_chunk(int f, int c, uint32_t dst, int tid) {
    const uint32_t* src = gW2h + (size_t)f * 128 * 132 + c * 32;
    #pragma unroll
    for (int i = 0; i < 8; i++) {
        int s = tid + i * NTH;          // s < 1024
        int nl = s >> 3, seg = s & 7;
        cpa16(dst + nl * 144 + seg * 16, src + (size_t)nl * 132 + seg * 4);
    }
}

// ---------------- main edge-MLP kernel (4 warps, m=32/warp, 2 CTAs/SM) -----
__global__ __launch_bounds__(NTH, 2)
void mlp_kernel(const int* __restrict__ ei, const float* __restrict__ ea,
                const float* __restrict__ b2o, const float* __restrict__ b2i,
                int E, float* __restrict__ out) {
    int f = blockIdx.y;
    int cnt = g_cnt[f];
    int base = blockIdx.x * TILE;
    if (base >= cnt) return;
    int nvalid = min(TILE, cnt - base);
    const int* list = g_list + f * MAX_E;
    int colOff = f ? 0 : 128;
    const float* b2 = f ? b2i : b2o;

    extern __shared__ __align__(16) char smem[];
    uint32_t sb = smem_u32(smem);
    uint32_t sbA = sb + SM_A;
    int tid = threadIdx.x, wid = tid >> 5, lane = tid & 31;
    int q = lane & 3;
    // 4 m-rows per thread: two m16 tiles at wid*32 and wid*32+16
    int m1 = wid * 32 + (lane >> 2);
    int m2 = m1 + 8, m3 = m1 + 16, m4 = m1 + 24;

    // P row byte-offsets (u32) from flavor base; node*1024 + q*256 < 4GB
    const char* Pb = (const char*)g_P + (size_t)f * NCAP * 1024;
    uint32_t poff[4];
    {
        int mm[4] = { m1, m2, m3, m4 };
        #pragma unroll
        for (int t = 0; t < 4; t++) {
            int e = __ldg(list + base + min(mm[t], nvalid - 1));
            int node = __ldg(ei + E + e);
            poff[t] = (uint32_t)node * 1024u + (uint32_t)q * 256u;
        }
    }

    // stream W1e (group 1): 2304 x 16B;  W2 chunks 0,1 (groups 2,3)
    {
        const uint32_t* src = gW1eh + (size_t)f * 256 * 36;
        #pragma unroll
        for (int i = 0; i < 18; i++) {
            int s = tid + i * NTH;
            cpa16(sb + SM_W1E + s * 16, src + s * 4);
        }
        CP_COMMIT();
    }
    cp_w2_chunk(f, 0, sb + SM_W2C, tid);          CP_COMMIT();
    cp_w2_chunk(f, 1, sb + SM_W2C + 18432, tid);  CP_COMMIT();

    // headers
    {
        int e = list[base + min(tid, nvalid - 1)];
        ((int*)(smem + SM_EIDX))[tid] = e;
        ((int*)(smem + SM_ROWS))[tid] = ei[e];
        ((float*)(smem + SM_B2))[tid] = b2[tid];
    }
    __syncthreads();

    // ---- gather A = edge_attr as f16, one full row per thread ----
    {
        int eidx = ((const int*)(smem + SM_EIDX))[tid];
        const float4* er = (const float4*)(ea + (size_t)eidx * 64);
        #pragma unroll
        for (int qq = 0; qq < 8; qq++) {
            float4 a = er[2 * qq], b = er[2 * qq + 1];
            sts128(sbA + tid * 144 + qq * 16,
                   pack_h2(a.x, a.y), pack_h2(a.z, a.w),
                   pack_h2(b.x, b.y), pack_h2(b.z, b.w));
        }
    }
    CP_WAIT(2);          // W1e resident
    __syncthreads();

    uint32_t bo144 = (uint32_t)((lane & 7) + ((lane >> 4) << 3)) * 144
                   + (uint32_t)(((lane >> 3) & 1) << 4);

    // A-fragments for both m16 tiles, all 4 k16-steps (held in regs)
    uint32_t af1[2][4][4];
    #pragma unroll
    for (int t = 0; t < 2; t++) {
        uint32_t aB = sbA + (wid * 32 + t * 16 + (lane & 15)) * 144 + (lane >> 4) * 16;
        #pragma unroll
        for (int s = 0; s < 4; s++) ldsm_x4(af1[t][s], aB + s * 32);
    }

    float acc2[2][16][4];
    #pragma unroll
    for (int t = 0; t < 2; t++)
        #pragma unroll
        for (int j = 0; j < 16; j++)
            #pragma unroll
            for (int p = 0; p < 4; p++) acc2[t][j][p] = 0.0f;

    uint32_t bW1 = sb + SM_W1E + bo144;

    // ---- fused loop: h n-tile pair j2 (GEMM1 into zero acc, +P after) ------
    #pragma unroll
    for (int c = 0; c < 4; c++) {
        if (c < 3) CP_WAIT(1); else CP_WAIT(0);
        __syncthreads();
        uint32_t bW2 = sb + SM_W2C + (c & 1) * 18432 + bo144;
        #pragma unroll
        for (int ks = 0; ks < 4; ks++) {
            int j2 = c * 4 + ks;
            // issue P loads up-front; first use is after the GEMM1 mma chain
            float4 pv0 = *(const float4*)(Pb + poff[0] + j2 * 16);
            float4 pv1 = *(const float4*)(Pb + poff[1] + j2 * 16);
            float4 pv2 = *(const float4*)(Pb + poff[2] + j2 * 16);
            float4 pv3 = *(const float4*)(Pb + poff[3] + j2 * 16);
            // GEMM1 into zero-initialized a1
            float a1[2][2][4] = {};
            #pragma unroll
            for (int s = 0; s < 4; s++) {
                uint32_t bf4[4];
                ldsm_x4(bf4, bW1 + j2 * 2304 + s * 32);
                #pragma unroll
                for (int t = 0; t < 2; t++) {
                    mma_f16(a1[t][0], af1[t][s], bf4);
                    mma_f16(a1[t][1], af1[t][s], bf4 + 2);
                }
            }
            // + P, relu, pack -> GEMM2 A-fragments
            uint32_t af[2][4];
            af[0][0] = pack_h2(fmaxf(a1[0][0][0] + pv0.x, 0.f),
                               fmaxf(a1[0][0][1] + pv0.y, 0.f));
            af[0][1] = pack_h2(fmaxf(a1[0][0][2] + pv1.x, 0.f),
                               fmaxf(a1[0][0][3] + pv1.y, 0.f));
            af[0][2] = pack_h2(fmaxf(a1[0][1][0] + pv0.z, 0.f),
                               fmaxf(a1[0][1][1] + pv0.w, 0.f));
            af[0][3] = pack_h2(fmaxf(a1[0][1][2] + pv1.z, 0.f),
                               fmaxf(a1[0][1][3] + pv1.w, 0.f));
            af[1][0] = pack_h2(fmaxf(a1[1][0][0] + pv2.x, 0.f),
                               fmaxf(a1[1][0][1] + pv2.y, 0.f));
            af[1][1] = pack_h2(fmaxf(a1[1][0][2] + pv3.x, 0.f),
                               fmaxf(a1[1][0][3] + pv3.y, 0.f));
            af[1][2] = pack_h2(fmaxf(a1[1][1][0] + pv2.z, 0.f),
                               fmaxf(a1[1][1][1] + pv2.w, 0.f));
            af[1][3] = pack_h2(fmaxf(a1[1][1][2] + pv3.z, 0.f),
                               fmaxf(a1[1][1][3] + pv3.w, 0.f));
            // GEMM2: B fragment shared across both m-tiles
            #pragma unroll
            for (int nt2 = 0; nt2 < 8; nt2++) {
                uint32_t bf4[4];
                ldsm_x4(bf4, bW2 + nt2 * 2304 + ks * 32);
                #pragma unroll
                for (int t = 0; t < 2; t++) {
                    mma_f16(acc2[t][2 * nt2],     af[t], bf4);
                    mma_f16(acc2[t][2 * nt2 + 1], af[t], bf4 + 2);
                }
            }
        }
        __syncthreads();
        if (c < 2) { cp_w2_chunk(f, c + 2, sb + SM_W2C + (c & 1) * 18432, tid); CP_COMMIT(); }
    }

    // ---- epilogue: + b2, vectorized scatter-add (4 m-rows per thread) ----
    {
        const float* b2s = (const float*)(smem + SM_B2);
        const int* rows = (const int*)(smem + SM_ROWS);
        int mm[4] = { m1, m2, m3, m4 };
        int t2 = 2 * q;
        #pragma unroll
        for (int t = 0; t < 4; t++) {
            bool ok = mm[t] < nvalid;
            if (!ok) continue;
            float* o = out + (size_t)rows[mm[t]] * 256 + colOff;
            int ti = t >> 1, hi = (t & 1) ? 2 : 0;
            #pragma unroll
            for (int nt = 0; nt < 16; nt++) {
                int n0 = 8 * nt + t2;
                red_add2(o + n0, acc2[ti][nt][hi] + b2s[n0],
                                 acc2[ti][nt][hi + 1] + b2s[n0 + 1]);
            }
        }
    }
}

// ---------------- host launch ----------------
extern "C" void kernel_launch(void* const* d_in, const int* in_sizes, int n_in,
                              void* d_out, int out_size) {
    const float* x   = (const float*)d_in[0];
    const int*   ei  = (const int*)  d_in[1];
    const float* ea  = (const float*)d_in[2];
    const float* W1o = (const float*)d_in[3];
    const float* b1o = (const float*)d_in[4];
    const float* W2o = (const float*)d_in[5];
    const float* b2o = (const float*)d_in[6];
    const float* W1i = (const float*)d_in[7];
    const float* b1i = (const float*)d_in[8];
    const float* W2i = (const float*)d_in[9];
    const float* b2i = (const float*)d_in[10];
    float* out = (float*)d_out;
    int E = in_sizes[1] / 2;
    int N = in_sizes[0] / 128;
    if (N > NCAP) N = NCAP;

    static bool attr_set = false;
    if (!attr_set) {
        cudaFuncSetAttribute(mlp_kernel, cudaFuncAttributeMaxDynamicSharedMemorySize,
                             SMEM_MLP);
        cudaFuncSetAttribute(pcomp_kernel, cudaFuncAttributeMaxDynamicSharedMemorySize,
                             SMEM_PC);
        attr_set = true;
    }

    cudaMemsetAsync(d_out, 0, (size_t)out_size * sizeof(float));
    prep_kernel<<<320, 256>>>(W1o, W1i, W2o, W2i);   // also resets g_cnt
    partition_kernel<<<(E + 511) / 512, 512>>>(ei, E);
    pcomp_kernel<<<dim3((N + 127) / 128, 2), 256, SMEM_PC>>>(x, b1o, b1i, N);

    dim3 grid((E + TILE - 1) / TILE, 2);
    mlp_kernel<<<grid, NTH, SMEM_MLP>>>(ei, ea, b2o, b2i, E, out);
}

// round 13
// speedup vs baseline: 1.9963x; 1.3096x over previous
#include <cuda_runtime.h>
#include <cuda_fp16.h>
#include <cstdint>

#define TILE   128
#define NTH    128
#define MAX_E  800000
#define NCAP   50048

// ---- mlp kernel smem layout (bytes) ----
#define SM_ROWS 0          // int[128]
#define SM_EIDX 512        // int[128]
#define SM_B2   1024       // float[128]
#define SM_A    1536       // 128 rows x 144 B: 18432 -> ends 19968
#define SM_W1E  19968      // 256 rows x 144 B: 36864 -> ends 56832
#define SM_W2C  56832      // 2 chunks x (128 rows x 144 B) = 36864 -> ends 93696
#define SMEM_MLP 93696

// ---- pcomp kernel smem layout ----
#define PC_B1   0          // float[256]
#define PC_A    1024       // 128 rows x 272 B: 34816
#define PC_W    35840      // 256 rows x 272 B: 69632
#define SMEM_PC 105472

__device__ int g_cnt[2];
__device__ int g_list[2 * MAX_E];
// packed fp16 weight images in smem (ldmatrix) layout, incl. row pads
__device__ uint32_t gW1eh[2 * 256 * 36];    // [f][n<256][kpair<32 +pad]
__device__ uint32_t gW1xh[2 * 256 * 68];    // [f][n<256][kpair<64 +pad]
__device__ uint32_t gW2h [2 * 128 * 132];   // [f][n<128][kpair<128 +pad]
// P in fp16, coalesced layout: [f][node][j2<16][q<4] uint2 (4 halves each)
// byte offset: node*512 + j2*32 + q*8
__device__ uint2 g_Ph[2 * (size_t)NCAP * 64];

// ---------------- helpers ----------------
static __device__ __forceinline__ uint32_t smem_u32(const void* p) {
    uint32_t a;
    asm("{ .reg .u64 t; cvta.to.shared.u64 t, %1; cvt.u32.u64 %0, t; }"
        : "=r"(a) : "l"(p));
    return a;
}
static __device__ __forceinline__ uint32_t pack_h2(float lo, float hi) {
    uint32_t r;
    asm("cvt.rn.f16x2.f32 %0, %1, %2;" : "=r"(r) : "f"(hi), "f"(lo));
    return r;
}
static __device__ __forceinline__ float2 unpack_h2(uint32_t u) {
    __half2 h = *reinterpret_cast<__half2*>(&u);
    return __half22float2(h);
}
static __device__ __forceinline__ void sts128(uint32_t a, uint32_t r0, uint32_t r1,
                                              uint32_t r2, uint32_t r3) {
    asm volatile("st.shared.v4.b32 [%0], {%1,%2,%3,%4};"
                 :: "r"(a), "r"(r0), "r"(r1), "r"(r2), "r"(r3) : "memory");
}
static __device__ __forceinline__ void ldsm_x4(uint32_t r[4], uint32_t addr) {
    asm volatile("ldmatrix.sync.aligned.m8n8.x4.shared.b16 {%0,%1,%2,%3}, [%4];"
                 : "=r"(r[0]), "=r"(r[1]), "=r"(r[2]), "=r"(r[3]) : "r"(addr));
}
static __device__ __forceinline__ void mma_f16(float d[4], const uint32_t a[4],
                                               const uint32_t b[2]) {
    asm("mma.sync.aligned.m16n8k16.row.col.f32.f16.f16.f32 "
        "{%0,%1,%2,%3}, {%4,%5,%6,%7}, {%8,%9}, {%0,%1,%2,%3};"
        : "+f"(d[0]), "+f"(d[1]), "+f"(d[2]), "+f"(d[3])
        : "r"(a[0]), "r"(a[1]), "r"(a[2]), "r"(a[3]), "r"(b[0]), "r"(b[1]));
}
static __device__ __forceinline__ void red_add2(float* p, float a, float b) {
    asm volatile("red.global.add.v2.f32 [%0], {%1,%2};"
                 :: "l"(p), "f"(a), "f"(b) : "memory");
}
static __device__ __forceinline__ void cpa16(uint32_t d, const void* s) {
    asm volatile("cp.async.ca.shared.global [%0], [%1], 16;"
                 :: "r"(d), "l"(s) : "memory");
}
#define CP_COMMIT() asm volatile("cp.async.commit_group;" ::: "memory")
#define CP_WAIT(n)  asm volatile("cp.async.wait_group %0;" :: "n"(n) : "memory")

// ---------------- setup kernels ----------------
__global__ void prep_kernel(const float* __restrict__ W1o, const float* __restrict__ W1i,
                            const float* __restrict__ W2o, const float* __restrict__ W2i) {
    int idx = blockIdx.x * 256 + threadIdx.x;
    if (idx < 2) g_cnt[idx] = 0;
    if (idx < 16384) {                          // W1e: [f][nl<256][p<32]
        int p = idx & 31; int t = idx >> 5;
        int nl = t & 255; int f = t >> 8;
        const float* W = f ? W1i : W1o;
        gW1eh[(f * 256 + nl) * 36 + p] =
            pack_h2(W[(128 + 2 * p) * 256 + nl], W[(129 + 2 * p) * 256 + nl]);
    } else if (idx < 49152) {                   // W1x: [f][nl<256][p<64]
        int i = idx - 16384;
        int p = i & 63; int t = i >> 6;
        int nl = t & 255; int f = t >> 8;
        const float* W = f ? W1i : W1o;
        gW1xh[(f * 256 + nl) * 68 + p] =
            pack_h2(W[(2 * p) * 256 + nl], W[(2 * p + 1) * 256 + nl]);
    } else if (idx < 81920) {                   // W2: [f][nl<128][p<128]
        int i = idx - 49152;
        int p = i & 127; int t = i >> 7;
        int nl = t & 127; int f = t >> 7;
        const float* W = f ? W2i : W2o;
        gW2h[(f * 128 + nl) * 132 + p] =
            pack_h2(W[(2 * p) * 128 + nl], W[(2 * p + 1) * 128 + nl]);
    }
}

__global__ void partition_kernel(const int* __restrict__ ei, int E) {
    __shared__ int s_cnt[2], s_base[2];
    int tid = threadIdx.x;
    if (tid < 2) s_cnt[tid] = 0;
    __syncthreads();
    int e = blockIdx.x * blockDim.x + tid;
    bool valid = e < E;
    int r = 0, c = 0;
    if (valid) { r = ei[e]; c = ei[E + e]; }
    int lane = tid & 31;
    bool po = valid && (r < c);
    bool pi = valid && (r > c);
    unsigned mo = __ballot_sync(0xffffffffu, po);
    unsigned mi = __ballot_sync(0xffffffffu, pi);
    int lo = __ffs(mo) - 1, li = __ffs(mi) - 1;
    int wo = 0, wi = 0;
    if (mo && lane == lo) wo = atomicAdd(&s_cnt[0], __popc(mo));
    if (mi && lane == li) wi = atomicAdd(&s_cnt[1], __popc(mi));
    __syncthreads();
    if (tid == 0) s_base[0] = atomicAdd(&g_cnt[0], s_cnt[0]);
    if (tid == 1) s_base[1] = atomicAdd(&g_cnt[1], s_cnt[1]);
    __syncthreads();
    if (mo) wo = __shfl_sync(0xffffffffu, wo, lo);
    if (mi) wi = __shfl_sync(0xffffffffu, wi, li);
    unsigned lt = (1u << lane) - 1u;
    if (po) g_list[s_base[0] + wo + __popc(mo & lt)] = e;
    if (pi) g_list[MAX_E + s_base[1] + wi + __popc(mi & lt)] = e;
}

// ---------------- P precompute: P = x @ W1x + b1 (fp16, [node][j2][q]) -----
__global__ __launch_bounds__(256, 1)
void pcomp_kernel(const float* __restrict__ x,
                  const float* __restrict__ b1o, const float* __restrict__ b1i,
                  int N) {
    int f = blockIdx.y;
    int base = blockIdx.x * 128;
    if (base >= N) return;
    const float* b1 = f ? b1i : b1o;

    extern __shared__ __align__(16) char smem[];
    uint32_t sb = smem_u32(smem);
    uint32_t sbA = sb + PC_A, sbW = sb + PC_W;
    int tid = threadIdx.x, wid = tid >> 5, lane = tid & 31;

    {
        const uint32_t* src = gW1xh + (size_t)f * 256 * 68;
        #pragma unroll
        for (int i = 0; i < 17; i++) {
            int s = tid + i * 256;
            cpa16(sbW + s * 16, src + s * 4);
        }
        CP_COMMIT();
    }
    ((float*)(smem + PC_B1))[tid] = b1[tid];

    {
        int r = tid & 127, h = tid >> 7;
        int node = min(base + r, N - 1);
        const float4* xr = (const float4*)(x + (size_t)node * 128);
        #pragma unroll
        for (int q = 0; q < 8; q++) {
            float4 a = xr[h * 16 + 2 * q], b = xr[h * 16 + 2 * q + 1];
            sts128(sbA + r * 272 + h * 128 + q * 16,
                   pack_h2(a.x, a.y), pack_h2(a.z, a.w),
                   pack_h2(b.x, b.y), pack_h2(b.z, b.w));
        }
    }
    CP_WAIT(0);
    __syncthreads();

    uint32_t aB = sbA + (wid * 16 + (lane & 15)) * 272 + (lane >> 4) * 16;
    uint32_t bB = sbW + (uint32_t)((lane & 7) + ((lane >> 4) << 3)) * 272
                + (uint32_t)(((lane >> 3) & 1) << 4);

    float acc[32][4];
    #pragma unroll
    for (int j = 0; j < 32; j++)
        #pragma unroll
        for (int p = 0; p < 4; p++) acc[j][p] = 0.0f;

    for (int s = 0; s < 8; s++) {
        uint32_t af[4]; ldsm_x4(af, aB + s * 32);
        #pragma unroll
        for (int nt2 = 0; nt2 < 16; nt2++) {
            uint32_t bf4[4];
            ldsm_x4(bf4, bB + nt2 * 4352 + s * 32);
            mma_f16(acc[2 * nt2],     af, bf4);
            mma_f16(acc[2 * nt2 + 1], af, bf4 + 2);
        }
    }

    // epilogue: + b1, pack fp16, write [node][j2][q] uint2
    {
        const float* b1s = (const float*)(smem + PC_B1);
        int q = lane & 3, t2 = 2 * q;
        int m1 = wid * 16 + (lane >> 2), m2 = m1 + 8;
        int n1 = base + m1, n2 = base + m2;
        uint2* p1 = g_Ph + ((size_t)f * NCAP + n1) * 64 + q;
        uint2* p2 = g_Ph + ((size_t)f * NCAP + n2) * 64 + q;
        #pragma unroll
        for (int j2 = 0; j2 < 16; j2++) {
            int j = 2 * j2;
            float b0 = b1s[8 * j + t2],       b1v = b1s[8 * j + t2 + 1];
            float b2v = b1s[8 * (j + 1) + t2], b3 = b1s[8 * (j + 1) + t2 + 1];
            if (n1 < N) {
                uint2 v;
                v.x = pack_h2(acc[j][0] + b0,     acc[j][1] + b1v);
                v.y = pack_h2(acc[j + 1][0] + b2v, acc[j + 1][1] + b3);
                p1[j2 * 4] = v;
            }
            if (n2 < N) {
                uint2 v;
                v.x = pack_h2(acc[j][2] + b0,     acc[j][3] + b1v);
                v.y = pack_h2(acc[j + 1][2] + b2v, acc[j + 1][3] + b3);
                p2[j2 * 4] = v;
            }
        }
    }
}

// ---------------- W2 quarter-chunk copy (32 kpairs = 128 B per n-row) -------
static __device__ __forceinline__ void cp_w2_chunk(int f, int c, uint32_t dst, int tid) {
    const uint32_t* src = gW2h + (size_t)f * 128 * 132 + c * 32;
    #pragma unroll
    for (int i = 0; i < 8; i++) {
        int s = tid + i * NTH;          // s < 1024
        int nl = s >> 3, seg = s & 7;
        cpa16(dst + nl * 144 + seg * 16, src + (size_t)nl * 132 + seg * 4);
    }
}

// ---------------- main edge-MLP kernel (4 warps, m=32/warp, 2 CTAs/SM) -----
__global__ __launch_bounds__(NTH, 2)
void mlp_kernel(const int* __restrict__ ei, const float* __restrict__ ea,
                const float* __restrict__ b2o, const float* __restrict__ b2i,
                int E, float* __restrict__ out) {
    int f = blockIdx.y;
    int cnt = g_cnt[f];
    int base = blockIdx.x * TILE;
    if (base >= cnt) return;
    int nvalid = min(TILE, cnt - base);
    const int* list = g_list + f * MAX_E;
    int colOff = f ? 0 : 128;
    const float* b2 = f ? b2i : b2o;

    extern __shared__ __align__(16) char smem[];
    uint32_t sb = smem_u32(smem);
    uint32_t sbA = sb + SM_A;
    int tid = threadIdx.x, wid = tid >> 5, lane = tid & 31;
    int q = lane & 3;
    int m1 = wid * 32 + (lane >> 2);
    int m2 = m1 + 8, m3 = m1 + 16, m4 = m1 + 24;

    // P byte-offsets: node*512 + q*8 (layout [node][j2][q], j2 stride 32 B)
    const char* Pb = (const char*)g_Ph + (size_t)f * NCAP * 512;
    uint32_t poff[4];
    {
        int mm[4] = { m1, m2, m3, m4 };
        #pragma unroll
        for (int t = 0; t < 4; t++) {
            int e = __ldg(list + base + min(mm[t], nvalid - 1));
            int node = __ldg(ei + E + e);
            poff[t] = (uint32_t)node * 512u + (uint32_t)q * 8u;
        }
    }

    // stream W1e (group 1): 2304 x 16B;  W2 chunks 0,1 (groups 2,3)
    {
        const uint32_t* src = gW1eh + (size_t)f * 256 * 36;
        #pragma unroll
        for (int i = 0; i < 18; i++) {
            int s = tid + i * NTH;
            cpa16(sb + SM_W1E + s * 16, src + s * 4);
        }
        CP_COMMIT();
    }
    cp_w2_chunk(f, 0, sb + SM_W2C, tid);          CP_COMMIT();
    cp_w2_chunk(f, 1, sb + SM_W2C + 18432, tid);  CP_COMMIT();

    // headers
    {
        int e = list[base + min(tid, nvalid - 1)];
        ((int*)(smem + SM_EIDX))[tid] = e;
        ((int*)(smem + SM_ROWS))[tid] = ei[e];
        ((float*)(smem + SM_B2))[tid] = b2[tid];
    }
    __syncthreads();

    // ---- gather A = edge_attr as f16, one full row per thread ----
    {
        int eidx = ((const int*)(smem + SM_EIDX))[tid];
        const float4* er = (const float4*)(ea + (size_t)eidx * 64);
        #pragma unroll
        for (int qq = 0; qq < 8; qq++) {
            float4 a = er[2 * qq], b = er[2 * qq + 1];
            sts128(sbA + tid * 144 + qq * 16,
                   pack_h2(a.x, a.y), pack_h2(a.z, a.w),
                   pack_h2(b.x, b.y), pack_h2(b.z, b.w));
        }
    }
    CP_WAIT(2);          // W1e resident
    __syncthreads();

    uint32_t bo144 = (uint32_t)((lane & 7) + ((lane >> 4) << 3)) * 144
                   + (uint32_t)(((lane >> 3) & 1) << 4);

    // A-fragments for both m16 tiles, all 4 k16-steps (held in regs)
    uint32_t af1[2][4][4];
    #pragma unroll
    for (int t = 0; t < 2; t++) {
        uint32_t aB = sbA + (wid * 32 + t * 16 + (lane & 15)) * 144 + (lane >> 4) * 16;
        #pragma unroll
        for (int s = 0; s < 4; s++) ldsm_x4(af1[t][s], aB + s * 32);
    }

    float acc2[2][16][4];
    #pragma unroll
    for (int t = 0; t < 2; t++)
        #pragma unroll
        for (int j = 0; j < 16; j++)
            #pragma unroll
            for (int p = 0; p < 4; p++) acc2[t][j][p] = 0.0f;

    uint32_t bW1 = sb + SM_W1E + bo144;

    // ---- fused loop: h n-tile pair j2 (GEMM1 into zero acc, +P after) ------
    #pragma unroll
    for (int c = 0; c < 4; c++) {
        if (c < 3) CP_WAIT(1); else CP_WAIT(0);
        __syncthreads();
        uint32_t bW2 = sb + SM_W2C + (c & 1) * 18432 + bo144;
        #pragma unroll
        for (int ks = 0; ks < 4; ks++) {
            int j2 = c * 4 + ks;
            // P loads: one coalesced uint2 per m-row (lanes q=0..3 contiguous)
            uint2 u0 = *(const uint2*)(Pb + poff[0] + j2 * 32);
            uint2 u1 = *(const uint2*)(Pb + poff[1] + j2 * 32);
            uint2 u2 = *(const uint2*)(Pb + poff[2] + j2 * 32);
            uint2 u3 = *(const uint2*)(Pb + poff[3] + j2 * 32);
            // GEMM1 into zero-initialized a1
            float a1[2][2][4] = {};
            #pragma unroll
            for (int s = 0; s < 4; s++) {
                uint32_t bf4[4];
                ldsm_x4(bf4, bW1 + j2 * 2304 + s * 32);
                #pragma unroll
                for (int t = 0; t < 2; t++) {
                    mma_f16(a1[t][0], af1[t][s], bf4);
                    mma_f16(a1[t][1], af1[t][s], bf4 + 2);
                }
            }
            // + P, relu, pack -> GEMM2 A-fragments
            uint32_t af[2][4];
            {
                float2 l0 = unpack_h2(u0.x), h0 = unpack_h2(u0.y);
                float2 l1 = unpack_h2(u1.x), h1 = unpack_h2(u1.y);
                af[0][0] = pack_h2(fmaxf(a1[0][0][0] + l0.x, 0.f),
                                   fmaxf(a1[0][0][1] + l0.y, 0.f));
                af[0][1] = pack_h2(fmaxf(a1[0][0][2] + l1.x, 0.f),
                                   fmaxf(a1[0][0][3] + l1.y, 0.f));
                af[0][2] = pack_h2(fmaxf(a1[0][1][0] + h0.x, 0.f),
                                   fmaxf(a1[0][1][1] + h0.y, 0.f));
                af[0][3] = pack_h2(fmaxf(a1[0][1][2] + h1.x, 0.f),
                                   fmaxf(a1[0][1][3] + h1.y, 0.f));
                float2 l2 = unpack_h2(u2.x), h2v = unpack_h2(u2.y);
                float2 l3 = unpack_h2(u3.x), h3 = unpack_h2(u3.y);
                af[1][0] = pack_h2(fmaxf(a1[1][0][0] + l2.x, 0.f),
                                   fmaxf(a1[1][0][1] + l2.y, 0.f));
                af[1][1] = pack_h2(fmaxf(a1[1][0][2] + l3.x, 0.f),
                                   fmaxf(a1[1][0][3] + l3.y, 0.f));
                af[1][2] = pack_h2(fmaxf(a1[1][1][0] + h2v.x, 0.f),
                                   fmaxf(a1[1][1][1] + h2v.y, 0.f));
                af[1][3] = pack_h2(fmaxf(a1[1][1][2] + h3.x, 0.f),
                                   fmaxf(a1[1][1][3] + h3.y, 0.f));
            }
            // GEMM2: B fragment shared across both m-tiles
            #pragma unroll
            for (int nt2 = 0; nt2 < 8; nt2++) {
                uint32_t bf4[4];
                ldsm_x4(bf4, bW2 + nt2 * 2304 + ks * 32);
                #pragma unroll
                for (int t = 0; t < 2; t++) {
                    mma_f16(acc2[t][2 * nt2],     af[t], bf4);
                    mma_f16(acc2[t][2 * nt2 + 1], af[t], bf4 + 2);
                }
            }
        }
        __syncthreads();
        if (c < 2) { cp_w2_chunk(f, c + 2, sb + SM_W2C + (c & 1) * 18432, tid); CP_COMMIT(); }
    }

    // ---- epilogue: + b2, vectorized scatter-add (4 m-rows per thread) ----
    {
        const float* b2s = (const float*)(smem + SM_B2);
        const int* rows = (const int*)(smem + SM_ROWS);
        int mm[4] = { m1, m2, m3, m4 };
        int t2 = 2 * q;
        #pragma unroll
        for (int t = 0; t < 4; t++) {
            bool ok = mm[t] < nvalid;
            if (!ok) continue;
            float* o = out + (size_t)rows[mm[t]] * 256 + colOff;
            int ti = t >> 1, hi = (t & 1) ? 2 : 0;
            #pragma unroll
            for (int nt = 0; nt < 16; nt++) {
                int n0 = 8 * nt + t2;
                red_add2(o + n0, acc2[ti][nt][hi] + b2s[n0],
                                 acc2[ti][nt][hi + 1] + b2s[n0 + 1]);
            }
        }
    }
}

// ---------------- host launch ----------------
extern "C" void kernel_launch(void* const* d_in, const int* in_sizes, int n_in,
                              void* d_out, int out_size) {
    const float* x   = (const float*)d_in[0];
    const int*   ei  = (const int*)  d_in[1];
    const float* ea  = (const float*)d_in[2];
    const float* W1o = (const float*)d_in[3];
    const float* b1o = (const float*)d_in[4];
    const float* W2o = (const float*)d_in[5];
    const float* b2o = (const float*)d_in[6];
    const float* W1i = (const float*)d_in[7];
    const float* b1i = (const float*)d_in[8];
    const float* W2i = (const float*)d_in[9];
    const float* b2i = (const float*)d_in[10];
    float* out = (float*)d_out;
    int E = in_sizes[1] / 2;
    int N = in_sizes[0] / 128;
    if (N > NCAP) N = NCAP;

    static bool attr_set = false;
    if (!attr_set) {
        cudaFuncSetAttribute(mlp_kernel, cudaFuncAttributeMaxDynamicSharedMemorySize,
                             SMEM_MLP);
        cudaFuncSetAttribute(pcomp_kernel, cudaFuncAttributeMaxDynamicSharedMemorySize,
                             SMEM_PC);
        attr_set = true;
    }

    cudaMemsetAsync(d_out, 0, (size_t)out_size * sizeof(float));
    prep_kernel<<<320, 256>>>(W1o, W1i, W2o, W2i);   // also resets g_cnt
    partition_kernel<<<(E + 511) / 512, 512>>>(ei, E);
    pcomp_kernel<<<dim3((N + 127) / 128, 2), 256, SMEM_PC>>>(x, b1o, b1i, N);

    dim3 grid((E + TILE - 1) / TILE, 2);
    mlp_kernel<<<grid, NTH, SMEM_MLP>>>(ei, ea, b2o, b2i, E, out);
}